// round 14
// baseline (speedup 1.0000x reference)
#include <cuda_runtime.h>
#include <cuda_fp16.h>
#include <math.h>
#include <stdint.h>

// ---------------- problem-size bounds (N=50000, E=400000 in dataset) ----------
#define MAXN 50176
#define MAXE 400384

// ---------------- device scratch (no mallocs allowed) -------------------------
__device__ __half  g_h1h[MAXN * 128];            // layer1 node embeddings (fp16)
__device__ float  g_res [MAXN * 128];            // residual res1
__device__ float  g_acc1[MAXN * 128];            // layer1 aggregate -> y -> BN input
__device__ __half  g_xh2[MAXN * 128];            // BN(y) fp16 (gemm2 input)
__device__ __half  g_h2h[(size_t)MAXN * 512];    // layer2 node embeddings (fp16)
__device__ float  g_s[MAXN * 4], g_d[MAXN * 4];  // attention src/dst terms
__device__ float  g_den[MAXN * 4];
__device__ float  g_alpha[MAXE * 4];             // layer2 ex values
__device__ float  g_e2[MAXE * 4];                // layer2 edge attention term
__device__ double g_colsum[128], g_colsq[128];
__device__ float  g_aew1T[4 * 64], g_aew2T[4 * 64];  // transposed [h][k]
__device__ float  g_eea1[4 * 4],  g_eea2[4 * 4];
__device__ float  g_ne1w1[3 * 128], g_ne2w2[3 * 512];
__device__ __half g_w2h[128 * 512];              // fp16 copies of weights
__device__ __half g_wresh[128 * 128];
__device__ __half g_w1h[32 * 128];
__device__ __half g_wres1h[32 * 128];

// ---------------- helpers ------------------------------------------------------
__device__ __forceinline__ void red4(float* p, float a, float b, float c, float d) {
    asm volatile("red.global.add.v4.f32 [%0], {%1,%2,%3,%4};"
                 :: "l"(p), "f"(a), "f"(b), "f"(c), "f"(d) : "memory");
}
__device__ __forceinline__ uint32_t smem_u32(const void* p) {
    return (uint32_t)__cvta_generic_to_shared(p);
}
__device__ __forceinline__ void ldsm_x4(uint32_t* r, uint32_t addr) {
    asm volatile("ldmatrix.sync.aligned.m8n8.x4.shared.b16 {%0,%1,%2,%3}, [%4];"
                 : "=r"(r[0]), "=r"(r[1]), "=r"(r[2]), "=r"(r[3]) : "r"(addr));
}
__device__ __forceinline__ void ldsm_x2t(uint32_t* r, uint32_t addr) {
    asm volatile("ldmatrix.sync.aligned.m8n8.x2.trans.shared.b16 {%0,%1}, [%2];"
                 : "=r"(r[0]), "=r"(r[1]) : "r"(addr));
}
__device__ __forceinline__ void mma16816(float* d, const uint32_t* a, const uint32_t* b) {
    asm volatile("mma.sync.aligned.m16n8k16.row.col.f32.f16.f16.f32 "
                 "{%0,%1,%2,%3}, {%4,%5,%6,%7}, {%8,%9}, {%0,%1,%2,%3};"
                 : "+f"(d[0]), "+f"(d[1]), "+f"(d[2]), "+f"(d[3])
                 : "r"(a[0]), "r"(a[1]), "r"(a[2]), "r"(a[3]), "r"(b[0]), "r"(b[1]));
}

// ---------------- precompute: fold linear maps (+ zero colsum) ------------------
__global__ void k_pre_a(const float* __restrict__ we1, const float* __restrict__ aedge1,
                        const float* __restrict__ we2, const float* __restrict__ aedge2,
                        const float* __restrict__ ne1, const float* __restrict__ w1,
                        const float* __restrict__ ne2, const float* __restrict__ w2) {
    int i = blockIdx.x * blockDim.x + threadIdx.x;
    if (i < 128) { g_colsum[i] = 0.0; g_colsq[i] = 0.0; }
    if (i < 256) {
        int k = i >> 2, h = i & 3; float a = 0.f;
        for (int c = 0; c < 32; c++) a += we1[k * 128 + h * 32 + c] * aedge1[h * 32 + c];
        g_aew1T[h * 64 + k] = a;
    } else if (i < 512) {
        int j = i - 256; int k = j >> 2, h = j & 3; float a = 0.f;
        for (int c = 0; c < 128; c++) a += we2[k * 512 + h * 128 + c] * aedge2[h * 128 + c];
        g_aew2T[h * 64 + k] = a;
    } else if (i < 896) {
        int j = i - 512; int t = j >> 7, col = j & 127; float a = 0.f;
        for (int k = 0; k < 32; k++) a += ne1[t * 32 + k] * w1[k * 128 + col];
        g_ne1w1[j] = a;
    } else if (i < 2432) {
        int j = i - 896; int t = j >> 9, col = j & 511; float a = 0.f;
        for (int k = 0; k < 128; k++) a += ne2[t * 128 + k] * w2[k * 512 + col];
        g_ne2w2[j] = a;
    }
}

__global__ void k_pre_b(const float* __restrict__ ee1, const float* __restrict__ ee2) {
    int i = threadIdx.x;
    if (i < 16) {
        int t = i >> 2, h = i & 3; float a = 0.f;
        for (int k = 0; k < 64; k++) a += ee1[t * 64 + k] * g_aew1T[h * 64 + k];
        g_eea1[i] = a;
    } else if (i < 32) {
        int j = i - 16; int t = j >> 2, h = j & 3; float a = 0.f;
        for (int k = 0; k < 64; k++) a += ee2[t * 64 + k] * g_aew2T[h * 64 + k];
        g_eea2[j] = a;
    }
}

// fp16 copies of all weights
__global__ void k_pre_w(const float* __restrict__ w2, const float* __restrict__ wres2,
                        const float* __restrict__ w1, const float* __restrict__ wres1) {
    int i = blockIdx.x * blockDim.x + threadIdx.x;
    if (i < 65536) g_w2h[i] = __float2half(w2[i]);
    else if (i < 81920) g_wresh[i - 65536] = __float2half(wres2[i - 65536]);
    else if (i < 86016) g_w1h[i - 81920] = __float2half(w1[i - 81920]);
    else if (i < 90112) g_wres1h[i - 86016] = __float2half(wres1[i - 86016]);
}

// ---------------- layer 1 GEMM v5: 64-row tile, fp16 HMMA, 3 CTA/SM ---------------
// smem: XH half[64][40] @0 (5120B) | WH half[32][136] @5120 (8704B)
//       Dsm fp32[64][130] overlays @0 (33280B) | sA@33280 sD@33792  total 34304B
__global__ void __launch_bounds__(256, 3)
k_gemm1(const float* __restrict__ x, const int* __restrict__ nt,
        const float* __restrict__ b1,
        const float* __restrict__ asrc, const float* __restrict__ adst, int N) {
    extern __shared__ __align__(16) char smraw[];
    __half* XH = reinterpret_cast<__half*>(smraw);            // [64][40]
    __half* WH = reinterpret_cast<__half*>(smraw + 5120);     // [32][136]
    float*  Dsm = reinterpret_cast<float*>(smraw);            // [64][130] (after)
    float*  sA = reinterpret_cast<float*>(smraw + 33280);
    float*  sD = reinterpret_cast<float*>(smraw + 33792);
    int t = threadIdx.x;           // 256
    int r0 = blockIdx.x * 64;
    int ct = blockIdx.y;           // 0: w1 + sd dots, 1: wres1 + acc zeroing
    int lane = t & 31, w = t >> 5;
    int warpM = w >> 2, warpN = w & 3;   // 2 x 4 warps: 32 rows x 32 cols each

    if (ct == 0 && t < 128) { sA[t] = asrc[t]; sD[t] = adst[t]; }

    // stage X fp16: 64 rows x 32 cols = 256 uint4
    {
        int r = t >> 2, kc = (t & 3) * 8;
        int gr = r0 + r;
        __half2 hh[4];
        if (gr < N) {
            float4 xa = *reinterpret_cast<const float4*>(&x[(size_t)gr * 32 + kc]);
            float4 xb = *reinterpret_cast<const float4*>(&x[(size_t)gr * 32 + kc + 4]);
            hh[0] = __floats2half2_rn(xa.x, xa.y);
            hh[1] = __floats2half2_rn(xa.z, xa.w);
            hh[2] = __floats2half2_rn(xb.x, xb.y);
            hh[3] = __floats2half2_rn(xb.z, xb.w);
        } else {
            hh[0] = hh[1] = hh[2] = hh[3] = __floats2half2_rn(0.f, 0.f);
        }
        *reinterpret_cast<uint4*>(&XH[r * 40 + kc]) = *reinterpret_cast<uint4*>(hh);
    }
    {
        const __half* wsrc = ct ? g_wres1h : g_w1h;
        for (int i = t; i < 512; i += 256) {
            int k = i >> 4, c8 = (i & 15) * 8;
            *reinterpret_cast<uint4*>(&WH[k * 136 + c8]) =
                *reinterpret_cast<const uint4*>(&wsrc[k * 128 + c8]);
        }
    }
    __syncthreads();

    float d[2][4][4];
    #pragma unroll
    for (int mf = 0; mf < 2; mf++)
        #pragma unroll
        for (int nf = 0; nf < 4; nf++)
            #pragma unroll
            for (int p = 0; p < 4; p++) d[mf][nf][p] = 0.f;

    uint32_t xh_b = smem_u32(XH);
    uint32_t wh_b = smem_u32(WH);
    int arow = lane & 15, acol = (lane >> 4) << 3;
    #pragma unroll
    for (int ks = 0; ks < 2; ks++) {
        int k0 = ks * 16;
        uint32_t a[2][4], b[4][2];
        #pragma unroll
        for (int mf = 0; mf < 2; mf++) {
            int m = warpM * 32 + mf * 16 + arow;
            ldsm_x4(a[mf], xh_b + (uint32_t)(m * 40 + k0 + acol) * 2u);
        }
        #pragma unroll
        for (int nf = 0; nf < 4; nf++) {
            int kk = k0 + (lane & 15);
            int n = warpN * 32 + nf * 8;
            ldsm_x2t(b[nf], wh_b + (uint32_t)(kk * 136 + n) * 2u);
        }
        #pragma unroll
        for (int mf = 0; mf < 2; mf++)
            #pragma unroll
            for (int nf = 0; nf < 4; nf++)
                mma16816(d[mf][nf], a[mf], b[nf]);
    }

    __syncthreads();
    #pragma unroll
    for (int mf = 0; mf < 2; mf++)
        #pragma unroll
        for (int nf = 0; nf < 4; nf++) {
            int row = warpM * 32 + mf * 16 + (lane >> 2);
            int col = warpN * 32 + nf * 8 + (lane & 3) * 2;
            *reinterpret_cast<float2*>(&Dsm[row * 130 + col]) =
                make_float2(d[mf][nf][0], d[mf][nf][1]);
            *reinterpret_cast<float2*>(&Dsm[(row + 8) * 130 + col]) =
                make_float2(d[mf][nf][2], d[mf][nf][3]);
        }
    __syncthreads();

    int tc = t & 15, tr = t >> 4;
    if (ct == 0) {
        float av[8], dv[8];
        #pragma unroll
        for (int i = 0; i < 8; i++) { av[i] = sA[tc * 8 + i]; dv[i] = sD[tc * 8 + i]; }
        int head = tc >> 2;
        #pragma unroll
        for (int j = 0; j < 4; j++) {
            int gr = r0 + tr * 4 + j;
            float o[8];
            const float* dr = &Dsm[(tr * 4 + j) * 130 + tc * 8];
            #pragma unroll
            for (int i = 0; i < 8; i++) o[i] = dr[i];
            int ty = (gr < N) ? nt[gr] : 0;
            const float* bias = &g_ne1w1[ty * 128 + tc * 8];
            float sp = 0.f, dp = 0.f;
            #pragma unroll
            for (int i = 0; i < 8; i++) {
                o[i] += bias[i];
                sp += o[i] * av[i];
                dp += o[i] * dv[i];
            }
            sp += __shfl_xor_sync(0xffffffffu, sp, 1);
            sp += __shfl_xor_sync(0xffffffffu, sp, 2);
            dp += __shfl_xor_sync(0xffffffffu, dp, 1);
            dp += __shfl_xor_sync(0xffffffffu, dp, 2);
            if (gr < N) {
                __half2 hh[4];
                #pragma unroll
                for (int p = 0; p < 4; p++) hh[p] = __floats2half2_rn(o[2 * p], o[2 * p + 1]);
                *reinterpret_cast<uint4*>(&g_h1h[(size_t)gr * 128 + tc * 8]) =
                    *reinterpret_cast<uint4*>(hh);
                if ((tc & 3) == 0) {
                    g_s[gr * 4 + head] = sp; g_d[gr * 4 + head] = dp;
                    g_den[gr * 4 + head] = 0.f;
                }
            }
        }
    } else {
        float bb[8];
        #pragma unroll
        for (int i = 0; i < 8; i++) bb[i] = b1[tc * 8 + i];
        float4 z4 = make_float4(0.f, 0.f, 0.f, 0.f);
        #pragma unroll
        for (int j = 0; j < 4; j++) {
            int gr = r0 + tr * 4 + j; if (gr >= N) continue;
            float o[8];
            const float* dr = &Dsm[(tr * 4 + j) * 130 + tc * 8];
            #pragma unroll
            for (int i = 0; i < 8; i++) o[i] = dr[i];
            float* dst = &g_res[(size_t)gr * 128 + tc * 8];
            *reinterpret_cast<float4*>(dst) =
                make_float4(o[0] + bb[0], o[1] + bb[1], o[2] + bb[2], o[3] + bb[3]);
            *reinterpret_cast<float4*>(dst + 4) =
                make_float4(o[4] + bb[4], o[5] + bb[5], o[6] + bb[6], o[7] + bb[7]);
            float* az = &g_acc1[(size_t)gr * 128 + tc * 8];
            *reinterpret_cast<float4*>(az)     = z4;
            *reinterpret_cast<float4*>(az + 4) = z4;
        }
    }
}

// ---------------- layer 1 fused edge phase (unchanged best) -----------------------
__global__ void __launch_bounds__(256)
k_edge1(const int* __restrict__ src, const int* __restrict__ dst,
        const float* __restrict__ ea, const int* __restrict__ et, int E) {
    __shared__ __align__(16) float sa1[4][64], sa2[4][64];
    __shared__ float se1[16], se2[16];
    int t = threadIdx.x;
    sa1[t >> 6][t & 63] = g_aew1T[t];
    sa2[t >> 6][t & 63] = g_aew2T[t];
    if (t < 16) { se1[t] = g_eea1[t]; se2[t] = g_eea2[t]; }
    __syncthreads();
    int l = t & 31, li = l & 7;
    int e = blockIdx.x * 32 + (t >> 5) * 4 + (l >> 3);
    bool valid = e < E;
    float e1[4] = {0, 0, 0, 0}, e2[4] = {0, 0, 0, 0};
    int s_ = 0, d_ = 0;
    if (valid) {
        s_ = src[e]; d_ = dst[e];
        const float* row = ea + (size_t)e * 64 + li * 8;
        float4 va = *reinterpret_cast<const float4*>(row);
        float4 vb = *reinterpret_cast<const float4*>(row + 4);
        float vs[8] = {va.x, va.y, va.z, va.w, vb.x, vb.y, vb.z, vb.w};
        #pragma unroll
        for (int h = 0; h < 4; h++) {
            float4 w0 = *reinterpret_cast<const float4*>(&sa1[h][li * 8]);
            float4 w1v = *reinterpret_cast<const float4*>(&sa1[h][li * 8 + 4]);
            float4 u0 = *reinterpret_cast<const float4*>(&sa2[h][li * 8]);
            float4 u1 = *reinterpret_cast<const float4*>(&sa2[h][li * 8 + 4]);
            e1[h] = vs[0]*w0.x + vs[1]*w0.y + vs[2]*w0.z + vs[3]*w0.w
                  + vs[4]*w1v.x + vs[5]*w1v.y + vs[6]*w1v.z + vs[7]*w1v.w;
            e2[h] = vs[0]*u0.x + vs[1]*u0.y + vs[2]*u0.z + vs[3]*u0.w
                  + vs[4]*u1.x + vs[5]*u1.y + vs[6]*u1.z + vs[7]*u1.w;
        }
    }
    #pragma unroll
    for (int h = 0; h < 4; h++)
        #pragma unroll
        for (int o = 1; o < 8; o <<= 1) {
            e1[h] += __shfl_xor_sync(0xffffffffu, e1[h], o);
            e2[h] += __shfl_xor_sync(0xffffffffu, e2[h], o);
        }
    float ex = 0.f;
    if (valid && li < 4) {
        float ev1 = (li == 0) ? e1[0] : (li == 1) ? e1[1] : (li == 2) ? e1[2] : e1[3];
        float ev2 = (li == 0) ? e2[0] : (li == 1) ? e2[1] : (li == 2) ? e2[2] : e2[3];
        int ty = et[e];
        float a = g_s[s_ * 4 + li] + g_d[d_ * 4 + li] + ev1 + se1[ty * 4 + li];
        a = (a >= 0.f) ? a : 0.2f * a;
        ex = __expf(a);
        atomicAdd(&g_den[d_ * 4 + li], ex);
        g_e2[e * 4 + li] = ev2 + se2[ty * 4 + li];
    }
    float exh = __shfl_sync(0xffffffffu, ex, (l & 24) + (li >> 1));
    if (valid) {
        const uint4* hb = reinterpret_cast<const uint4*>(&g_h1h[(size_t)s_ * 128 + li * 16]);
        float* ab = &g_acc1[(size_t)d_ * 128 + li * 16];
        #pragma unroll
        for (int q = 0; q < 2; q++) {
            uint4 pk = hb[q];
            __half2* hp = reinterpret_cast<__half2*>(&pk);
            float2 f0 = __half22float2(hp[0]);
            float2 f1 = __half22float2(hp[1]);
            float2 f2 = __half22float2(hp[2]);
            float2 f3 = __half22float2(hp[3]);
            red4(ab + q * 8,     f0.x * exh, f0.y * exh, f1.x * exh, f1.y * exh);
            red4(ab + q * 8 + 4, f2.x * exh, f2.y * exh, f3.x * exh, f3.y * exh);
        }
    }
}

// ---------------- BN stats: y = acc1/den + res (softmax norm fused) --------------
__global__ void k_bnstats(int N) {
    int t = threadIdx.x;
    int hh = t >> 5;
    double s = 0.0, q = 0.0;
    for (int n = blockIdx.x; n < N; n += gridDim.x) {
        float den = g_den[n * 4 + hh] + 1e-16f;
        float y = g_acc1[(size_t)n * 128 + t] / den + g_res[(size_t)n * 128 + t];
        g_acc1[(size_t)n * 128 + t] = y;
        s += y; q += (double)y * y;
    }
    atomicAdd(&g_colsum[t], s);
    atomicAdd(&g_colsq[t], q);
}

// BN finalize + apply in one pass: per-block scale/shift from colsum, fp16 output
__global__ void __launch_bounds__(256)
k_bnapply(const float* __restrict__ gamma, const float* __restrict__ beta, int N) {
    __shared__ float sScale[128], sShift[128];
    int t = threadIdx.x;
    if (t < 128) {
        double mu = g_colsum[t] / N;
        double var = g_colsq[t] / N - mu * mu;
        double sc = (double)gamma[t] / sqrt(var + 1e-5);
        sScale[t] = (float)sc;
        sShift[t] = (float)((double)beta[t] - mu * sc);
    }
    __syncthreads();
    int i = blockIdx.x * 256 + t;   // one uint4 (8 halves) per thread
    if (i >= N * 16) return;
    int kc = (i & 15) * 8;
    size_t base = (size_t)(i >> 4) * 128 + kc;
    float4 xa = *reinterpret_cast<const float4*>(&g_acc1[base]);
    float4 xb = *reinterpret_cast<const float4*>(&g_acc1[base + 4]);
    __half2 hh[4];
    hh[0] = __floats2half2_rn(xa.x * sScale[kc]     + sShift[kc],
                              xa.y * sScale[kc + 1] + sShift[kc + 1]);
    hh[1] = __floats2half2_rn(xa.z * sScale[kc + 2] + sShift[kc + 2],
                              xa.w * sScale[kc + 3] + sShift[kc + 3]);
    hh[2] = __floats2half2_rn(xb.x * sScale[kc + 4] + sShift[kc + 4],
                              xb.y * sScale[kc + 5] + sShift[kc + 5]);
    hh[3] = __floats2half2_rn(xb.z * sScale[kc + 6] + sShift[kc + 6],
                              xb.w * sScale[kc + 7] + sShift[kc + 7]);
    *reinterpret_cast<uint4*>(&g_xh2[base]) = *reinterpret_cast<uint4*>(hh);
}

// ---------------- layer 2 GEMM: fp16 tensor-core; ct=4 writes res2 -> d_out -------
__global__ void __launch_bounds__(256, 2)
k_gemm2(const int* __restrict__ nt, const float* __restrict__ b2,
        const float* __restrict__ asrc, const float* __restrict__ adst,
        float* __restrict__ outp, int N) {
    extern __shared__ __align__(16) char smraw[];
    __half* XH = reinterpret_cast<__half*>(smraw);                  // [128][136]
    __half* WH = reinterpret_cast<__half*>(smraw + 34816);          // [128][136]
    float*  Dsm = reinterpret_cast<float*>(smraw);                  // [128][130] (after)
    int t = threadIdx.x;
    int r0 = blockIdx.x * 128;
    int ct = blockIdx.y;
    int lane = t & 31, w = t >> 5;
    int warpM = w >> 2, warpN = w & 3;

    for (int i = t; i < 2048; i += 256) {
        int r = i >> 4, c8 = (i & 15) * 8;
        int gr = r0 + r;
        uint4 v = make_uint4(0u, 0u, 0u, 0u);
        if (gr < N) v = *reinterpret_cast<const uint4*>(&g_xh2[(size_t)gr * 128 + c8]);
        *reinterpret_cast<uint4*>(&XH[r * 136 + c8]) = v;
    }
    {
        const __half* wsrc = (ct < 4) ? &g_w2h[ct * 128] : g_wresh;
        int wstride = (ct < 4) ? 512 : 128;
        for (int i = t; i < 2048; i += 256) {
            int k = i >> 4, c8 = (i & 15) * 8;
            *reinterpret_cast<uint4*>(&WH[k * 136 + c8]) =
                *reinterpret_cast<const uint4*>(&wsrc[(size_t)k * wstride + c8]);
        }
    }
    __syncthreads();

    float d[4][4][4];
    #pragma unroll
    for (int mf = 0; mf < 4; mf++)
        #pragma unroll
        for (int nf = 0; nf < 4; nf++)
            #pragma unroll
            for (int p = 0; p < 4; p++) d[mf][nf][p] = 0.f;

    uint32_t xh_b = smem_u32(XH);
    uint32_t wh_b = smem_u32(WH);
    int arow = lane & 15, acol = (lane >> 4) << 3;
    #pragma unroll
    for (int ks = 0; ks < 8; ks++) {
        int k0 = ks * 16;
        uint32_t a[4][4], b[4][2];
        #pragma unroll
        for (int mf = 0; mf < 4; mf++) {
            int m = warpM * 64 + mf * 16 + arow;
            ldsm_x4(a[mf], xh_b + (uint32_t)(m * 136 + k0 + acol) * 2u);
        }
        #pragma unroll
        for (int nf = 0; nf < 4; nf++) {
            int kk = k0 + (lane & 15);
            int n = warpN * 32 + nf * 8;
            ldsm_x2t(b[nf], wh_b + (uint32_t)(kk * 136 + n) * 2u);
        }
        #pragma unroll
        for (int mf = 0; mf < 4; mf++)
            #pragma unroll
            for (int nf = 0; nf < 4; nf++)
                mma16816(d[mf][nf], a[mf], b[nf]);
    }

    __syncthreads();
    #pragma unroll
    for (int mf = 0; mf < 4; mf++)
        #pragma unroll
        for (int nf = 0; nf < 4; nf++) {
            int row = warpM * 64 + mf * 16 + (lane >> 2);
            int col = warpN * 32 + nf * 8 + (lane & 3) * 2;
            *reinterpret_cast<float2*>(&Dsm[row * 130 + col]) =
                make_float2(d[mf][nf][0], d[mf][nf][1]);
            *reinterpret_cast<float2*>(&Dsm[(row + 8) * 130 + col]) =
                make_float2(d[mf][nf][2], d[mf][nf][3]);
        }
    __syncthreads();

    int tc = t & 15, tr = t >> 4;
    if (ct < 4) {
        float av[8], dv[8];
        #pragma unroll
        for (int i = 0; i < 8; i++) {
            av[i] = asrc[ct * 128 + tc * 8 + i];
            dv[i] = adst[ct * 128 + tc * 8 + i];
        }
        #pragma unroll
        for (int j = 0; j < 8; j++) {
            int gr = r0 + tr * 8 + j;
            float o[8];
            const float* dr = &Dsm[(tr * 8 + j) * 130 + tc * 8];
            #pragma unroll
            for (int i = 0; i < 8; i++) o[i] = dr[i];
            int ty = (gr < N) ? nt[gr] : 0;
            const float* bias = &g_ne2w2[ty * 512 + ct * 128 + tc * 8];
            float sp = 0.f, dp = 0.f;
            #pragma unroll
            for (int i = 0; i < 8; i++) {
                o[i] += bias[i];
                sp += o[i] * av[i];
                dp += o[i] * dv[i];
            }
            #pragma unroll
            for (int off = 8; off; off >>= 1) {
                sp += __shfl_xor_sync(0xffffffffu, sp, off);
                dp += __shfl_xor_sync(0xffffffffu, dp, off);
            }
            if (gr < N) {
                __half2 hh[4];
                #pragma unroll
                for (int p = 0; p < 4; p++) hh[p] = __floats2half2_rn(o[2 * p], o[2 * p + 1]);
                *reinterpret_cast<uint4*>(&g_h2h[(size_t)gr * 512 + ct * 128 + tc * 8]) =
                    *reinterpret_cast<uint4*>(hh);
                if (tc == 0) {
                    g_s[gr * 4 + ct] = sp; g_d[gr * 4 + ct] = dp;
                    g_den[gr * 4 + ct] = 0.f;
                }
            }
        }
    } else {
        #pragma unroll
        for (int j = 0; j < 8; j++) {
            int gr = r0 + tr * 8 + j; if (gr >= N) continue;
            float o[8];
            const float* dr = &Dsm[(tr * 8 + j) * 130 + tc * 8];
            #pragma unroll
            for (int i = 0; i < 8; i++) o[i] = dr[i];
            const float* bias = &b2[tc * 8];
            float* dst = &outp[(size_t)gr * 128 + tc * 8];
            *reinterpret_cast<float4*>(dst) =
                make_float4(o[0] + bias[0], o[1] + bias[1], o[2] + bias[2], o[3] + bias[3]);
            *reinterpret_cast<float4*>(dst + 4) =
                make_float4(o[4] + bias[4], o[5] + bias[5], o[6] + bias[6], o[7] + bias[7]);
        }
    }
}

// ---------------- layer 2 edge pass A: one thread per edge, vectorized ------------
__global__ void k_edge2A(const int* __restrict__ src, const int* __restrict__ dst, int E) {
    int e = blockIdx.x * blockDim.x + threadIdx.x;
    if (e >= E) return;
    int s_ = src[e], d_ = dst[e];
    float4 sv = *reinterpret_cast<const float4*>(&g_s[s_ * 4]);
    float4 dv = *reinterpret_cast<const float4*>(&g_d[d_ * 4]);
    float4 ev = *reinterpret_cast<const float4*>(&g_e2[e * 4]);
    float a0 = sv.x + dv.x + ev.x; a0 = (a0 >= 0.f) ? a0 : 0.2f * a0;
    float a1 = sv.y + dv.y + ev.y; a1 = (a1 >= 0.f) ? a1 : 0.2f * a1;
    float a2 = sv.z + dv.z + ev.z; a2 = (a2 >= 0.f) ? a2 : 0.2f * a2;
    float a3 = sv.w + dv.w + ev.w; a3 = (a3 >= 0.f) ? a3 : 0.2f * a3;
    float e0 = __expf(a0), e1 = __expf(a1), e2v = __expf(a2), e3 = __expf(a3);
    *reinterpret_cast<float4*>(&g_alpha[e * 4]) = make_float4(e0, e1, e2v, e3);
    float* dn = &g_den[d_ * 4];
    atomicAdd(dn,     e0);
    atomicAdd(dn + 1, e1);
    atomicAdd(dn + 2, e2v);
    atomicAdd(dn + 3, e3);
}

// ---------------- edge aggregate layer 2: red4 directly into d_out ----------------
__global__ void k_aggr2(const int* __restrict__ src, const int* __restrict__ dst,
                        float* __restrict__ outp, int E) {
    int e = blockIdx.x * 8 + (threadIdx.x >> 5); if (e >= E) return;
    int l = threadIdx.x & 31;
    int s_ = src[e], d_ = dst[e];
    float cf = 0.f;
    if (l < 4) cf = 0.25f * g_alpha[e * 4 + l] / (g_den[d_ * 4 + l] + 1e-16f);
    int m = l & 15, hp = l >> 4;
    float ca = __shfl_sync(0xffffffffu, cf, 2 * hp);
    float cb = __shfl_sync(0xffffffffu, cf, 2 * hp + 1);
    const uint4* hs = reinterpret_cast<const uint4*>(&g_h2h[(size_t)s_ * 512]);
    uint4 qa = hs[hp * 32 + m];
    uint4 qb = hs[hp * 32 + 16 + m];
    __half2* pa = reinterpret_cast<__half2*>(&qa);
    __half2* pb = reinterpret_cast<__half2*>(&qb);
    float r[8];
    #pragma unroll
    for (int i = 0; i < 4; i++) {
        float2 fa = __half22float2(pa[i]);
        float2 fb = __half22float2(pb[i]);
        r[2 * i]     = ca * fa.x + cb * fb.x;
        r[2 * i + 1] = ca * fa.y + cb * fb.y;
    }
    #pragma unroll
    for (int i = 0; i < 8; i++) r[i] += __shfl_xor_sync(0xffffffffu, r[i], 16);
    if (l < 16) {
        float* ab = &outp[(size_t)d_ * 128 + m * 8];
        red4(ab,     r[0], r[1], r[2], r[3]);
        red4(ab + 4, r[4], r[5], r[6], r[7]);
    }
}

// ---------------- host launch ----------------------------------------------------
extern "C" void kernel_launch(void* const* d_in, const int* in_sizes, int n_in,
                              void* d_out, int out_size) {
    const float* x      = (const float*)d_in[0];
    const int*   ei     = (const int*)  d_in[1];
    const int*   nt     = (const int*)  d_in[2];
    const float* ea     = (const float*)d_in[3];
    const int*   et     = (const int*)  d_in[4];
    const float* ne1    = (const float*)d_in[5];
    const float* w1     = (const float*)d_in[6];
    const float* we1    = (const float*)d_in[7];
    const float* asrc1  = (const float*)d_in[8];
    const float* adst1  = (const float*)d_in[9];
    const float* aedge1 = (const float*)d_in[10];
    const float* ee1    = (const float*)d_in[11];
    const float* wres1  = (const float*)d_in[12];
    const float* b1     = (const float*)d_in[13];
    const float* gamma  = (const float*)d_in[14];
    const float* beta   = (const float*)d_in[15];
    const float* ne2    = (const float*)d_in[16];
    const float* w2     = (const float*)d_in[17];
    const float* we2    = (const float*)d_in[18];
    const float* asrc2  = (const float*)d_in[19];
    const float* adst2  = (const float*)d_in[20];
    const float* aedge2 = (const float*)d_in[21];
    const float* ee2    = (const float*)d_in[22];
    const float* wres2  = (const float*)d_in[23];
    const float* b2     = (const float*)d_in[24];

    int N = in_sizes[0] / 32;
    int E = in_sizes[4];
    const int* src = ei;
    const int* dstp = ei + E;
    float* outp = (float*)d_out;

    // ---- precompute ----
    k_pre_a<<<10, 256>>>(we1, aedge1, we2, aedge2, ne1, w1, ne2, w2);
    k_pre_b<<<1, 32>>>(ee1, ee2);
    k_pre_w<<<352, 256>>>(w2, wres2, w1, wres1);

    // ---- layer 1 (tensor-core gemm1, 64-row tiles) ----
    size_t smem1 = 34304;
    cudaFuncSetAttribute(k_gemm1, cudaFuncAttributeMaxDynamicSharedMemorySize, (int)smem1);
    dim3 g1((N + 63) / 64, 2);
    k_gemm1<<<g1, 256, smem1>>>(x, nt, b1, asrc1, adst1, N);
    k_edge1<<<(E + 31) / 32, 256>>>(src, dstp, ea, et, E);

    // ---- batch norm (stats, then fused finalize+apply) ----
    k_bnstats<<<592, 128>>>(N);
    k_bnapply<<<(N * 16 + 255) / 256, 256>>>(gamma, beta, N);

    // ---- layer 2 (tensor-core gemm2; ct=4 writes res2 into d_out) ----
    size_t smem2 = 69632;
    cudaFuncSetAttribute(k_gemm2, cudaFuncAttributeMaxDynamicSharedMemorySize, (int)smem2);
    dim3 g2((N + 127) / 128, 5);
    k_gemm2<<<g2, 256, smem2>>>(nt, b2, asrc2, adst2, outp, N);
    k_edge2A<<<(E + 255) / 256, 256>>>(src, dstp, E);
    k_aggr2<<<(E + 7) / 8, 256>>>(src, dstp, outp, E);
}

// round 15
// speedup vs baseline: 1.0097x; 1.0097x over previous
#include <cuda_runtime.h>
#include <cuda_fp16.h>
#include <math.h>
#include <stdint.h>

// ---------------- problem-size bounds (N=50000, E=400000 in dataset) ----------
#define MAXN 50176
#define MAXE 400384

// ---------------- device scratch (no mallocs allowed) -------------------------
__device__ __half  g_h1h[MAXN * 128];            // layer1 node embeddings (fp16)
__device__ float  g_res [MAXN * 128];            // residual res1
__device__ float  g_acc1[MAXN * 128];            // layer1 aggregate -> y -> BN input
__device__ __half  g_xh2[MAXN * 128];            // BN(y) fp16 (gemm2 input)
__device__ __half  g_h2h[(size_t)MAXN * 512];    // layer2 node embeddings (fp16)
__device__ float  g_s[MAXN * 4], g_d[MAXN * 4];  // attention src/dst terms
__device__ float  g_den[MAXN * 4];
__device__ float  g_alpha[MAXE * 4];             // layer2 ex values
__device__ float  g_e2[MAXE * 4];                // layer2 edge attention term
__device__ double g_colsum[128], g_colsq[128];
__device__ float  g_aew1T[4 * 64], g_aew2T[4 * 64];  // transposed [h][k]
__device__ float  g_eea1[4 * 4],  g_eea2[4 * 4];
__device__ float  g_ne1w1[3 * 128], g_ne2w2[3 * 512];
__device__ __half g_w2h[128 * 512];              // fp16 copies of weights
__device__ __half g_wresh[128 * 128];
__device__ __half g_w1h[32 * 128];
__device__ __half g_wres1h[32 * 128];

// ---------------- helpers ------------------------------------------------------
__device__ __forceinline__ void red4(float* p, float a, float b, float c, float d) {
    asm volatile("red.global.add.v4.f32 [%0], {%1,%2,%3,%4};"
                 :: "l"(p), "f"(a), "f"(b), "f"(c), "f"(d) : "memory");
}
__device__ __forceinline__ uint32_t smem_u32(const void* p) {
    return (uint32_t)__cvta_generic_to_shared(p);
}
__device__ __forceinline__ void ldsm_x4(uint32_t* r, uint32_t addr) {
    asm volatile("ldmatrix.sync.aligned.m8n8.x4.shared.b16 {%0,%1,%2,%3}, [%4];"
                 : "=r"(r[0]), "=r"(r[1]), "=r"(r[2]), "=r"(r[3]) : "r"(addr));
}
__device__ __forceinline__ void ldsm_x2t(uint32_t* r, uint32_t addr) {
    asm volatile("ldmatrix.sync.aligned.m8n8.x2.trans.shared.b16 {%0,%1}, [%2];"
                 : "=r"(r[0]), "=r"(r[1]) : "r"(addr));
}
__device__ __forceinline__ void mma16816(float* d, const uint32_t* a, const uint32_t* b) {
    asm volatile("mma.sync.aligned.m16n8k16.row.col.f32.f16.f16.f32 "
                 "{%0,%1,%2,%3}, {%4,%5,%6,%7}, {%8,%9}, {%0,%1,%2,%3};"
                 : "+f"(d[0]), "+f"(d[1]), "+f"(d[2]), "+f"(d[3])
                 : "r"(a[0]), "r"(a[1]), "r"(a[2]), "r"(a[3]), "r"(b[0]), "r"(b[1]));
}

// ---------------- precompute: fold linear maps (+ zero colsum) ------------------
__global__ void k_pre_a(const float* __restrict__ we1, const float* __restrict__ aedge1,
                        const float* __restrict__ we2, const float* __restrict__ aedge2,
                        const float* __restrict__ ne1, const float* __restrict__ w1,
                        const float* __restrict__ ne2, const float* __restrict__ w2) {
    int i = blockIdx.x * blockDim.x + threadIdx.x;
    if (i < 128) { g_colsum[i] = 0.0; g_colsq[i] = 0.0; }
    if (i < 256) {
        int k = i >> 2, h = i & 3; float a = 0.f;
        for (int c = 0; c < 32; c++) a += we1[k * 128 + h * 32 + c] * aedge1[h * 32 + c];
        g_aew1T[h * 64 + k] = a;
    } else if (i < 512) {
        int j = i - 256; int k = j >> 2, h = j & 3; float a = 0.f;
        for (int c = 0; c < 128; c++) a += we2[k * 512 + h * 128 + c] * aedge2[h * 128 + c];
        g_aew2T[h * 64 + k] = a;
    } else if (i < 896) {
        int j = i - 512; int t = j >> 7, col = j & 127; float a = 0.f;
        for (int k = 0; k < 32; k++) a += ne1[t * 32 + k] * w1[k * 128 + col];
        g_ne1w1[j] = a;
    } else if (i < 2432) {
        int j = i - 896; int t = j >> 9, col = j & 511; float a = 0.f;
        for (int k = 0; k < 128; k++) a += ne2[t * 128 + k] * w2[k * 512 + col];
        g_ne2w2[j] = a;
    }
}

__global__ void k_pre_b(const float* __restrict__ ee1, const float* __restrict__ ee2) {
    int i = threadIdx.x;
    if (i < 16) {
        int t = i >> 2, h = i & 3; float a = 0.f;
        for (int k = 0; k < 64; k++) a += ee1[t * 64 + k] * g_aew1T[h * 64 + k];
        g_eea1[i] = a;
    } else if (i < 32) {
        int j = i - 16; int t = j >> 2, h = j & 3; float a = 0.f;
        for (int k = 0; k < 64; k++) a += ee2[t * 64 + k] * g_aew2T[h * 64 + k];
        g_eea2[j] = a;
    }
}

// fp16 copies of all weights
__global__ void k_pre_w(const float* __restrict__ w2, const float* __restrict__ wres2,
                        const float* __restrict__ w1, const float* __restrict__ wres1) {
    int i = blockIdx.x * blockDim.x + threadIdx.x;
    if (i < 65536) g_w2h[i] = __float2half(w2[i]);
    else if (i < 81920) g_wresh[i - 65536] = __float2half(wres2[i - 65536]);
    else if (i < 86016) g_w1h[i - 81920] = __float2half(w1[i - 81920]);
    else if (i < 90112) g_wres1h[i - 86016] = __float2half(wres1[i - 86016]);
}

// ---------------- layer 1 GEMM: 64-row tile, fp16 HMMA, 3 CTA/SM ------------------
__global__ void __launch_bounds__(256, 3)
k_gemm1(const float* __restrict__ x, const int* __restrict__ nt,
        const float* __restrict__ b1,
        const float* __restrict__ asrc, const float* __restrict__ adst, int N) {
    extern __shared__ __align__(16) char smraw[];
    __half* XH = reinterpret_cast<__half*>(smraw);            // [64][40]
    __half* WH = reinterpret_cast<__half*>(smraw + 5120);     // [32][136]
    float*  Dsm = reinterpret_cast<float*>(smraw);            // [64][130] (after)
    float*  sA = reinterpret_cast<float*>(smraw + 33280);
    float*  sD = reinterpret_cast<float*>(smraw + 33792);
    int t = threadIdx.x;           // 256
    int r0 = blockIdx.x * 64;
    int ct = blockIdx.y;           // 0: w1 + sd dots, 1: wres1 + acc zeroing
    int lane = t & 31, w = t >> 5;
    int warpM = w >> 2, warpN = w & 3;

    if (ct == 0 && t < 128) { sA[t] = asrc[t]; sD[t] = adst[t]; }

    {
        int r = t >> 2, kc = (t & 3) * 8;
        int gr = r0 + r;
        __half2 hh[4];
        if (gr < N) {
            float4 xa = *reinterpret_cast<const float4*>(&x[(size_t)gr * 32 + kc]);
            float4 xb = *reinterpret_cast<const float4*>(&x[(size_t)gr * 32 + kc + 4]);
            hh[0] = __floats2half2_rn(xa.x, xa.y);
            hh[1] = __floats2half2_rn(xa.z, xa.w);
            hh[2] = __floats2half2_rn(xb.x, xb.y);
            hh[3] = __floats2half2_rn(xb.z, xb.w);
        } else {
            hh[0] = hh[1] = hh[2] = hh[3] = __floats2half2_rn(0.f, 0.f);
        }
        *reinterpret_cast<uint4*>(&XH[r * 40 + kc]) = *reinterpret_cast<uint4*>(hh);
    }
    {
        const __half* wsrc = ct ? g_wres1h : g_w1h;
        for (int i = t; i < 512; i += 256) {
            int k = i >> 4, c8 = (i & 15) * 8;
            *reinterpret_cast<uint4*>(&WH[k * 136 + c8]) =
                *reinterpret_cast<const uint4*>(&wsrc[k * 128 + c8]);
        }
    }
    __syncthreads();

    float d[2][4][4];
    #pragma unroll
    for (int mf = 0; mf < 2; mf++)
        #pragma unroll
        for (int nf = 0; nf < 4; nf++)
            #pragma unroll
            for (int p = 0; p < 4; p++) d[mf][nf][p] = 0.f;

    uint32_t xh_b = smem_u32(XH);
    uint32_t wh_b = smem_u32(WH);
    int arow = lane & 15, acol = (lane >> 4) << 3;
    #pragma unroll
    for (int ks = 0; ks < 2; ks++) {
        int k0 = ks * 16;
        uint32_t a[2][4], b[4][2];
        #pragma unroll
        for (int mf = 0; mf < 2; mf++) {
            int m = warpM * 32 + mf * 16 + arow;
            ldsm_x4(a[mf], xh_b + (uint32_t)(m * 40 + k0 + acol) * 2u);
        }
        #pragma unroll
        for (int nf = 0; nf < 4; nf++) {
            int kk = k0 + (lane & 15);
            int n = warpN * 32 + nf * 8;
            ldsm_x2t(b[nf], wh_b + (uint32_t)(kk * 136 + n) * 2u);
        }
        #pragma unroll
        for (int mf = 0; mf < 2; mf++)
            #pragma unroll
            for (int nf = 0; nf < 4; nf++)
                mma16816(d[mf][nf], a[mf], b[nf]);
    }

    __syncthreads();
    #pragma unroll
    for (int mf = 0; mf < 2; mf++)
        #pragma unroll
        for (int nf = 0; nf < 4; nf++) {
            int row = warpM * 32 + mf * 16 + (lane >> 2);
            int col = warpN * 32 + nf * 8 + (lane & 3) * 2;
            *reinterpret_cast<float2*>(&Dsm[row * 130 + col]) =
                make_float2(d[mf][nf][0], d[mf][nf][1]);
            *reinterpret_cast<float2*>(&Dsm[(row + 8) * 130 + col]) =
                make_float2(d[mf][nf][2], d[mf][nf][3]);
        }
    __syncthreads();

    int tc = t & 15, tr = t >> 4;
    if (ct == 0) {
        float av[8], dv[8];
        #pragma unroll
        for (int i = 0; i < 8; i++) { av[i] = sA[tc * 8 + i]; dv[i] = sD[tc * 8 + i]; }
        int head = tc >> 2;
        #pragma unroll
        for (int j = 0; j < 4; j++) {
            int gr = r0 + tr * 4 + j;
            float o[8];
            const float* dr = &Dsm[(tr * 4 + j) * 130 + tc * 8];
            #pragma unroll
            for (int i = 0; i < 8; i++) o[i] = dr[i];
            int ty = (gr < N) ? nt[gr] : 0;
            const float* bias = &g_ne1w1[ty * 128 + tc * 8];
            float sp = 0.f, dp = 0.f;
            #pragma unroll
            for (int i = 0; i < 8; i++) {
                o[i] += bias[i];
                sp += o[i] * av[i];
                dp += o[i] * dv[i];
            }
            sp += __shfl_xor_sync(0xffffffffu, sp, 1);
            sp += __shfl_xor_sync(0xffffffffu, sp, 2);
            dp += __shfl_xor_sync(0xffffffffu, dp, 1);
            dp += __shfl_xor_sync(0xffffffffu, dp, 2);
            if (gr < N) {
                __half2 hh[4];
                #pragma unroll
                for (int p = 0; p < 4; p++) hh[p] = __floats2half2_rn(o[2 * p], o[2 * p + 1]);
                *reinterpret_cast<uint4*>(&g_h1h[(size_t)gr * 128 + tc * 8]) =
                    *reinterpret_cast<uint4*>(hh);
                if ((tc & 3) == 0) {
                    g_s[gr * 4 + head] = sp; g_d[gr * 4 + head] = dp;
                    g_den[gr * 4 + head] = 0.f;
                }
            }
        }
    } else {
        float bb[8];
        #pragma unroll
        for (int i = 0; i < 8; i++) bb[i] = b1[tc * 8 + i];
        float4 z4 = make_float4(0.f, 0.f, 0.f, 0.f);
        #pragma unroll
        for (int j = 0; j < 4; j++) {
            int gr = r0 + tr * 4 + j; if (gr >= N) continue;
            float o[8];
            const float* dr = &Dsm[(tr * 4 + j) * 130 + tc * 8];
            #pragma unroll
            for (int i = 0; i < 8; i++) o[i] = dr[i];
            float* dst = &g_res[(size_t)gr * 128 + tc * 8];
            *reinterpret_cast<float4*>(dst) =
                make_float4(o[0] + bb[0], o[1] + bb[1], o[2] + bb[2], o[3] + bb[3]);
            *reinterpret_cast<float4*>(dst + 4) =
                make_float4(o[4] + bb[4], o[5] + bb[5], o[6] + bb[6], o[7] + bb[7]);
            float* az = &g_acc1[(size_t)gr * 128 + tc * 8];
            *reinterpret_cast<float4*>(az)     = z4;
            *reinterpret_cast<float4*>(az + 4) = z4;
        }
    }
}

// ---------------- layer 1 fused edge phase (unchanged best) -----------------------
__global__ void __launch_bounds__(256)
k_edge1(const int* __restrict__ src, const int* __restrict__ dst,
        const float* __restrict__ ea, const int* __restrict__ et, int E) {
    __shared__ __align__(16) float sa1[4][64], sa2[4][64];
    __shared__ float se1[16], se2[16];
    int t = threadIdx.x;
    sa1[t >> 6][t & 63] = g_aew1T[t];
    sa2[t >> 6][t & 63] = g_aew2T[t];
    if (t < 16) { se1[t] = g_eea1[t]; se2[t] = g_eea2[t]; }
    __syncthreads();
    int l = t & 31, li = l & 7;
    int e = blockIdx.x * 32 + (t >> 5) * 4 + (l >> 3);
    bool valid = e < E;
    float e1[4] = {0, 0, 0, 0}, e2[4] = {0, 0, 0, 0};
    int s_ = 0, d_ = 0;
    if (valid) {
        s_ = src[e]; d_ = dst[e];
        const float* row = ea + (size_t)e * 64 + li * 8;
        float4 va = *reinterpret_cast<const float4*>(row);
        float4 vb = *reinterpret_cast<const float4*>(row + 4);
        float vs[8] = {va.x, va.y, va.z, va.w, vb.x, vb.y, vb.z, vb.w};
        #pragma unroll
        for (int h = 0; h < 4; h++) {
            float4 w0 = *reinterpret_cast<const float4*>(&sa1[h][li * 8]);
            float4 w1v = *reinterpret_cast<const float4*>(&sa1[h][li * 8 + 4]);
            float4 u0 = *reinterpret_cast<const float4*>(&sa2[h][li * 8]);
            float4 u1 = *reinterpret_cast<const float4*>(&sa2[h][li * 8 + 4]);
            e1[h] = vs[0]*w0.x + vs[1]*w0.y + vs[2]*w0.z + vs[3]*w0.w
                  + vs[4]*w1v.x + vs[5]*w1v.y + vs[6]*w1v.z + vs[7]*w1v.w;
            e2[h] = vs[0]*u0.x + vs[1]*u0.y + vs[2]*u0.z + vs[3]*u0.w
                  + vs[4]*u1.x + vs[5]*u1.y + vs[6]*u1.z + vs[7]*u1.w;
        }
    }
    #pragma unroll
    for (int h = 0; h < 4; h++)
        #pragma unroll
        for (int o = 1; o < 8; o <<= 1) {
            e1[h] += __shfl_xor_sync(0xffffffffu, e1[h], o);
            e2[h] += __shfl_xor_sync(0xffffffffu, e2[h], o);
        }
    float ex = 0.f;
    if (valid && li < 4) {
        float ev1 = (li == 0) ? e1[0] : (li == 1) ? e1[1] : (li == 2) ? e1[2] : e1[3];
        float ev2 = (li == 0) ? e2[0] : (li == 1) ? e2[1] : (li == 2) ? e2[2] : e2[3];
        int ty = et[e];
        float a = g_s[s_ * 4 + li] + g_d[d_ * 4 + li] + ev1 + se1[ty * 4 + li];
        a = (a >= 0.f) ? a : 0.2f * a;
        ex = __expf(a);
        atomicAdd(&g_den[d_ * 4 + li], ex);
        g_e2[e * 4 + li] = ev2 + se2[ty * 4 + li];
    }
    float exh = __shfl_sync(0xffffffffu, ex, (l & 24) + (li >> 1));
    if (valid) {
        const uint4* hb = reinterpret_cast<const uint4*>(&g_h1h[(size_t)s_ * 128 + li * 16]);
        float* ab = &g_acc1[(size_t)d_ * 128 + li * 16];
        #pragma unroll
        for (int q = 0; q < 2; q++) {
            uint4 pk = hb[q];
            __half2* hp = reinterpret_cast<__half2*>(&pk);
            float2 f0 = __half22float2(hp[0]);
            float2 f1 = __half22float2(hp[1]);
            float2 f2 = __half22float2(hp[2]);
            float2 f3 = __half22float2(hp[3]);
            red4(ab + q * 8,     f0.x * exh, f0.y * exh, f1.x * exh, f1.y * exh);
            red4(ab + q * 8 + 4, f2.x * exh, f2.y * exh, f3.x * exh, f3.y * exh);
        }
    }
}

// ---------------- BN stats: y = acc1/den + res (softmax norm fused) --------------
__global__ void k_bnstats(int N) {
    int t = threadIdx.x;
    int hh = t >> 5;
    double s = 0.0, q = 0.0;
    for (int n = blockIdx.x; n < N; n += gridDim.x) {
        float den = g_den[n * 4 + hh] + 1e-16f;
        float y = g_acc1[(size_t)n * 128 + t] / den + g_res[(size_t)n * 128 + t];
        g_acc1[(size_t)n * 128 + t] = y;
        s += y; q += (double)y * y;
    }
    atomicAdd(&g_colsum[t], s);
    atomicAdd(&g_colsq[t], q);
}

// BN finalize + apply in one pass: per-block scale/shift from colsum, fp16 output
__global__ void __launch_bounds__(256)
k_bnapply(const float* __restrict__ gamma, const float* __restrict__ beta, int N) {
    __shared__ float sScale[128], sShift[128];
    int t = threadIdx.x;
    if (t < 128) {
        double mu = g_colsum[t] / N;
        double var = g_colsq[t] / N - mu * mu;
        double sc = (double)gamma[t] / sqrt(var + 1e-5);
        sScale[t] = (float)sc;
        sShift[t] = (float)((double)beta[t] - mu * sc);
    }
    __syncthreads();
    int i = blockIdx.x * 256 + t;
    if (i >= N * 16) return;
    int kc = (i & 15) * 8;
    size_t base = (size_t)(i >> 4) * 128 + kc;
    float4 xa = *reinterpret_cast<const float4*>(&g_acc1[base]);
    float4 xb = *reinterpret_cast<const float4*>(&g_acc1[base + 4]);
    __half2 hh[4];
    hh[0] = __floats2half2_rn(xa.x * sScale[kc]     + sShift[kc],
                              xa.y * sScale[kc + 1] + sShift[kc + 1]);
    hh[1] = __floats2half2_rn(xa.z * sScale[kc + 2] + sShift[kc + 2],
                              xa.w * sScale[kc + 3] + sShift[kc + 3]);
    hh[2] = __floats2half2_rn(xb.x * sScale[kc + 4] + sShift[kc + 4],
                              xb.y * sScale[kc + 5] + sShift[kc + 5]);
    hh[3] = __floats2half2_rn(xb.z * sScale[kc + 6] + sShift[kc + 6],
                              xb.w * sScale[kc + 7] + sShift[kc + 7]);
    *reinterpret_cast<uint4*>(&g_xh2[base]) = *reinterpret_cast<uint4*>(hh);
}

// ---------------- layer 2 GEMM: fp16 tensor-core; ct=4 writes res2 -> d_out -------
__global__ void __launch_bounds__(256, 2)
k_gemm2(const int* __restrict__ nt, const float* __restrict__ b2,
        const float* __restrict__ asrc, const float* __restrict__ adst,
        float* __restrict__ outp, int N) {
    extern __shared__ __align__(16) char smraw[];
    __half* XH = reinterpret_cast<__half*>(smraw);                  // [128][136]
    __half* WH = reinterpret_cast<__half*>(smraw + 34816);          // [128][136]
    float*  Dsm = reinterpret_cast<float*>(smraw);                  // [128][130] (after)
    int t = threadIdx.x;
    int r0 = blockIdx.x * 128;
    int ct = blockIdx.y;
    int lane = t & 31, w = t >> 5;
    int warpM = w >> 2, warpN = w & 3;

    for (int i = t; i < 2048; i += 256) {
        int r = i >> 4, c8 = (i & 15) * 8;
        int gr = r0 + r;
        uint4 v = make_uint4(0u, 0u, 0u, 0u);
        if (gr < N) v = *reinterpret_cast<const uint4*>(&g_xh2[(size_t)gr * 128 + c8]);
        *reinterpret_cast<uint4*>(&XH[r * 136 + c8]) = v;
    }
    {
        const __half* wsrc = (ct < 4) ? &g_w2h[ct * 128] : g_wresh;
        int wstride = (ct < 4) ? 512 : 128;
        for (int i = t; i < 2048; i += 256) {
            int k = i >> 4, c8 = (i & 15) * 8;
            *reinterpret_cast<uint4*>(&WH[k * 136 + c8]) =
                *reinterpret_cast<const uint4*>(&wsrc[(size_t)k * wstride + c8]);
        }
    }
    __syncthreads();

    float d[4][4][4];
    #pragma unroll
    for (int mf = 0; mf < 4; mf++)
        #pragma unroll
        for (int nf = 0; nf < 4; nf++)
            #pragma unroll
            for (int p = 0; p < 4; p++) d[mf][nf][p] = 0.f;

    uint32_t xh_b = smem_u32(XH);
    uint32_t wh_b = smem_u32(WH);
    int arow = lane & 15, acol = (lane >> 4) << 3;
    #pragma unroll
    for (int ks = 0; ks < 8; ks++) {
        int k0 = ks * 16;
        uint32_t a[4][4], b[4][2];
        #pragma unroll
        for (int mf = 0; mf < 4; mf++) {
            int m = warpM * 64 + mf * 16 + arow;
            ldsm_x4(a[mf], xh_b + (uint32_t)(m * 136 + k0 + acol) * 2u);
        }
        #pragma unroll
        for (int nf = 0; nf < 4; nf++) {
            int kk = k0 + (lane & 15);
            int n = warpN * 32 + nf * 8;
            ldsm_x2t(b[nf], wh_b + (uint32_t)(kk * 136 + n) * 2u);
        }
        #pragma unroll
        for (int mf = 0; mf < 4; mf++)
            #pragma unroll
            for (int nf = 0; nf < 4; nf++)
                mma16816(d[mf][nf], a[mf], b[nf]);
    }

    __syncthreads();
    #pragma unroll
    for (int mf = 0; mf < 4; mf++)
        #pragma unroll
        for (int nf = 0; nf < 4; nf++) {
            int row = warpM * 64 + mf * 16 + (lane >> 2);
            int col = warpN * 32 + nf * 8 + (lane & 3) * 2;
            *reinterpret_cast<float2*>(&Dsm[row * 130 + col]) =
                make_float2(d[mf][nf][0], d[mf][nf][1]);
            *reinterpret_cast<float2*>(&Dsm[(row + 8) * 130 + col]) =
                make_float2(d[mf][nf][2], d[mf][nf][3]);
        }
    __syncthreads();

    int tc = t & 15, tr = t >> 4;
    if (ct < 4) {
        float av[8], dv[8];
        #pragma unroll
        for (int i = 0; i < 8; i++) {
            av[i] = asrc[ct * 128 + tc * 8 + i];
            dv[i] = adst[ct * 128 + tc * 8 + i];
        }
        #pragma unroll
        for (int j = 0; j < 8; j++) {
            int gr = r0 + tr * 8 + j;
            float o[8];
            const float* dr = &Dsm[(tr * 8 + j) * 130 + tc * 8];
            #pragma unroll
            for (int i = 0; i < 8; i++) o[i] = dr[i];
            int ty = (gr < N) ? nt[gr] : 0;
            const float* bias = &g_ne2w2[ty * 512 + ct * 128 + tc * 8];
            float sp = 0.f, dp = 0.f;
            #pragma unroll
            for (int i = 0; i < 8; i++) {
                o[i] += bias[i];
                sp += o[i] * av[i];
                dp += o[i] * dv[i];
            }
            #pragma unroll
            for (int off = 8; off; off >>= 1) {
                sp += __shfl_xor_sync(0xffffffffu, sp, off);
                dp += __shfl_xor_sync(0xffffffffu, dp, off);
            }
            if (gr < N) {
                __half2 hh[4];
                #pragma unroll
                for (int p = 0; p < 4; p++) hh[p] = __floats2half2_rn(o[2 * p], o[2 * p + 1]);
                *reinterpret_cast<uint4*>(&g_h2h[(size_t)gr * 512 + ct * 128 + tc * 8]) =
                    *reinterpret_cast<uint4*>(hh);
                if (tc == 0) {
                    g_s[gr * 4 + ct] = sp; g_d[gr * 4 + ct] = dp;
                    g_den[gr * 4 + ct] = 0.f;
                }
            }
        }
    } else {
        #pragma unroll
        for (int j = 0; j < 8; j++) {
            int gr = r0 + tr * 8 + j; if (gr >= N) continue;
            float o[8];
            const float* dr = &Dsm[(tr * 8 + j) * 130 + tc * 8];
            #pragma unroll
            for (int i = 0; i < 8; i++) o[i] = dr[i];
            const float* bias = &b2[tc * 8];
            float* dst = &outp[(size_t)gr * 128 + tc * 8];
            *reinterpret_cast<float4*>(dst) =
                make_float4(o[0] + bias[0], o[1] + bias[1], o[2] + bias[2], o[3] + bias[3]);
            *reinterpret_cast<float4*>(dst + 4) =
                make_float4(o[4] + bias[4], o[5] + bias[5], o[6] + bias[6], o[7] + bias[7]);
        }
    }
}

// ---------------- layer 2 edge pass A (round-13 proven form) -----------------------
__global__ void k_edge2A(const int* __restrict__ src, const int* __restrict__ dst, int E) {
    int i = blockIdx.x * blockDim.x + threadIdx.x;
    if (i >= E * 4) return;
    int e = i >> 2, h = i & 3;
    int s_ = src[e], d_ = dst[e];
    float a = g_s[s_ * 4 + h] + g_d[d_ * 4 + h] + g_e2[i];
    a = (a >= 0.f) ? a : 0.2f * a;
    float ex = __expf(a);
    g_alpha[i] = ex;
    atomicAdd(&g_den[d_ * 4 + h], ex);
}

// ---------------- edge aggregate layer 2: red4 directly into d_out ----------------
__global__ void k_aggr2(const int* __restrict__ src, const int* __restrict__ dst,
                        float* __restrict__ outp, int E) {
    int e = blockIdx.x * 8 + (threadIdx.x >> 5); if (e >= E) return;
    int l = threadIdx.x & 31;
    int s_ = src[e], d_ = dst[e];
    float cf = 0.f;
    if (l < 4) cf = 0.25f * g_alpha[e * 4 + l] / (g_den[d_ * 4 + l] + 1e-16f);
    int m = l & 15, hp = l >> 4;
    float ca = __shfl_sync(0xffffffffu, cf, 2 * hp);
    float cb = __shfl_sync(0xffffffffu, cf, 2 * hp + 1);
    const uint4* hs = reinterpret_cast<const uint4*>(&g_h2h[(size_t)s_ * 512]);
    uint4 qa = hs[hp * 32 + m];
    uint4 qb = hs[hp * 32 + 16 + m];
    __half2* pa = reinterpret_cast<__half2*>(&qa);
    __half2* pb = reinterpret_cast<__half2*>(&qb);
    float r[8];
    #pragma unroll
    for (int i = 0; i < 4; i++) {
        float2 fa = __half22float2(pa[i]);
        float2 fb = __half22float2(pb[i]);
        r[2 * i]     = ca * fa.x + cb * fb.x;
        r[2 * i + 1] = ca * fa.y + cb * fb.y;
    }
    #pragma unroll
    for (int i = 0; i < 8; i++) r[i] += __shfl_xor_sync(0xffffffffu, r[i], 16);
    if (l < 16) {
        float* ab = &outp[(size_t)d_ * 128 + m * 8];
        red4(ab,     r[0], r[1], r[2], r[3]);
        red4(ab + 4, r[4], r[5], r[6], r[7]);
    }
}

// ---------------- host launch ----------------------------------------------------
extern "C" void kernel_launch(void* const* d_in, const int* in_sizes, int n_in,
                              void* d_out, int out_size) {
    const float* x      = (const float*)d_in[0];
    const int*   ei     = (const int*)  d_in[1];
    const int*   nt     = (const int*)  d_in[2];
    const float* ea     = (const float*)d_in[3];
    const int*   et     = (const int*)  d_in[4];
    const float* ne1    = (const float*)d_in[5];
    const float* w1     = (const float*)d_in[6];
    const float* we1    = (const float*)d_in[7];
    const float* asrc1  = (const float*)d_in[8];
    const float* adst1  = (const float*)d_in[9];
    const float* aedge1 = (const float*)d_in[10];
    const float* ee1    = (const float*)d_in[11];
    const float* wres1  = (const float*)d_in[12];
    const float* b1     = (const float*)d_in[13];
    const float* gamma  = (const float*)d_in[14];
    const float* beta   = (const float*)d_in[15];
    const float* ne2    = (const float*)d_in[16];
    const float* w2     = (const float*)d_in[17];
    const float* we2    = (const float*)d_in[18];
    const float* asrc2  = (const float*)d_in[19];
    const float* adst2  = (const float*)d_in[20];
    const float* aedge2 = (const float*)d_in[21];
    const float* ee2    = (const float*)d_in[22];
    const float* wres2  = (const float*)d_in[23];
    const float* b2     = (const float*)d_in[24];

    int N = in_sizes[0] / 32;
    int E = in_sizes[4];
    const int* src = ei;
    const int* dstp = ei + E;
    float* outp = (float*)d_out;

    // ---- precompute ----
    k_pre_a<<<10, 256>>>(we1, aedge1, we2, aedge2, ne1, w1, ne2, w2);
    k_pre_b<<<1, 32>>>(ee1, ee2);
    k_pre_w<<<352, 256>>>(w2, wres2, w1, wres1);

    // ---- layer 1 (tensor-core gemm1, 64-row tiles) ----
    size_t smem1 = 34304;
    cudaFuncSetAttribute(k_gemm1, cudaFuncAttributeMaxDynamicSharedMemorySize, (int)smem1);
    dim3 g1((N + 63) / 64, 2);
    k_gemm1<<<g1, 256, smem1>>>(x, nt, b1, asrc1, adst1, N);
    k_edge1<<<(E + 31) / 32, 256>>>(src, dstp, ea, et, E);

    // ---- batch norm (stats, then fused finalize+apply) ----
    k_bnstats<<<592, 128>>>(N);
    k_bnapply<<<(N * 16 + 255) / 256, 256>>>(gamma, beta, N);

    // ---- layer 2 (tensor-core gemm2; ct=4 writes res2 into d_out) ----
    size_t smem2 = 69632;
    cudaFuncSetAttribute(k_gemm2, cudaFuncAttributeMaxDynamicSharedMemorySize, (int)smem2);
    dim3 g2((N + 127) / 128, 5);
    k_gemm2<<<g2, 256, smem2>>>(nt, b2, asrc2, adst2, outp, N);
    k_edge2A<<<(E * 4 + 255) / 256, 256>>>(src, dstp, E);
    k_aggr2<<<(E + 7) / 8, 256>>>(src, dstp, outp, E);
}

// round 16
// speedup vs baseline: 1.0435x; 1.0335x over previous
#include <cuda_runtime.h>
#include <cuda_fp16.h>
#include <math.h>
#include <stdint.h>

// ---------------- problem-size bounds (N=50000, E=400000 in dataset) ----------
#define MAXN 50176
#define MAXE 400384

// ---------------- device scratch (no mallocs allowed) -------------------------
__device__ __half  g_h1h[MAXN * 128];            // layer1 node embeddings (fp16)
__device__ float  g_res [MAXN * 128];            // residual res1
__device__ float  g_acc1[MAXN * 128];            // layer1 aggregate -> y -> BN input
__device__ __half  g_xh2[MAXN * 128];            // BN(y) fp16 (gemm2 input)
__device__ __half  g_h2h[(size_t)MAXN * 512];    // layer2 node embeddings (fp16)
__device__ float  g_s[MAXN * 4], g_d[MAXN * 4];  // attention src/dst terms
__device__ float  g_den[MAXN * 4];
__device__ float  g_alpha[MAXE * 4];             // layer2 ex values
__device__ float  g_e2[MAXE * 4];                // layer2 edge attention term
__device__ double g_colsum[128], g_colsq[128];
__device__ float  g_scale[128], g_shift[128];
__device__ float  g_aew1T[4 * 64], g_aew2T[4 * 64];  // transposed [h][k]
__device__ float  g_eea1[4 * 4],  g_eea2[4 * 4];
__device__ float  g_ne1w1[3 * 128], g_ne2w2[3 * 512];
__device__ __half g_w2h[128 * 512];              // fp16 copies of weights
__device__ __half g_wresh[128 * 128];
__device__ __half g_w1h[32 * 128];
__device__ __half g_wres1h[32 * 128];

// ---------------- helpers ------------------------------------------------------
__device__ __forceinline__ void red4(float* p, float a, float b, float c, float d) {
    asm volatile("red.global.add.v4.f32 [%0], {%1,%2,%3,%4};"
                 :: "l"(p), "f"(a), "f"(b), "f"(c), "f"(d) : "memory");
}
__device__ __forceinline__ uint32_t smem_u32(const void* p) {
    return (uint32_t)__cvta_generic_to_shared(p);
}
__device__ __forceinline__ void ldsm_x4(uint32_t* r, uint32_t addr) {
    asm volatile("ldmatrix.sync.aligned.m8n8.x4.shared.b16 {%0,%1,%2,%3}, [%4];"
                 : "=r"(r[0]), "=r"(r[1]), "=r"(r[2]), "=r"(r[3]) : "r"(addr));
}
__device__ __forceinline__ void ldsm_x2t(uint32_t* r, uint32_t addr) {
    asm volatile("ldmatrix.sync.aligned.m8n8.x2.trans.shared.b16 {%0,%1}, [%2];"
                 : "=r"(r[0]), "=r"(r[1]) : "r"(addr));
}
__device__ __forceinline__ void mma16816(float* d, const uint32_t* a, const uint32_t* b) {
    asm volatile("mma.sync.aligned.m16n8k16.row.col.f32.f16.f16.f32 "
                 "{%0,%1,%2,%3}, {%4,%5,%6,%7}, {%8,%9}, {%0,%1,%2,%3};"
                 : "+f"(d[0]), "+f"(d[1]), "+f"(d[2]), "+f"(d[3])
                 : "r"(a[0]), "r"(a[1]), "r"(a[2]), "r"(a[3]), "r"(b[0]), "r"(b[1]));
}

// ---------------- precompute: fold linear maps (+ zero colsum) ------------------
__global__ void k_pre_a(const float* __restrict__ we1, const float* __restrict__ aedge1,
                        const float* __restrict__ we2, const float* __restrict__ aedge2,
                        const float* __restrict__ ne1, const float* __restrict__ w1,
                        const float* __restrict__ ne2, const float* __restrict__ w2) {
    int i = blockIdx.x * blockDim.x + threadIdx.x;
    if (i < 128) { g_colsum[i] = 0.0; g_colsq[i] = 0.0; }
    if (i < 256) {
        int k = i >> 2, h = i & 3; float a = 0.f;
        for (int c = 0; c < 32; c++) a += we1[k * 128 + h * 32 + c] * aedge1[h * 32 + c];
        g_aew1T[h * 64 + k] = a;
    } else if (i < 512) {
        int j = i - 256; int k = j >> 2, h = j & 3; float a = 0.f;
        for (int c = 0; c < 128; c++) a += we2[k * 512 + h * 128 + c] * aedge2[h * 128 + c];
        g_aew2T[h * 64 + k] = a;
    } else if (i < 896) {
        int j = i - 512; int t = j >> 7, col = j & 127; float a = 0.f;
        for (int k = 0; k < 32; k++) a += ne1[t * 32 + k] * w1[k * 128 + col];
        g_ne1w1[j] = a;
    } else if (i < 2432) {
        int j = i - 896; int t = j >> 9, col = j & 511; float a = 0.f;
        for (int k = 0; k < 128; k++) a += ne2[t * 128 + k] * w2[k * 512 + col];
        g_ne2w2[j] = a;
    }
}

__global__ void k_pre_b(const float* __restrict__ ee1, const float* __restrict__ ee2) {
    int i = threadIdx.x;
    if (i < 16) {
        int t = i >> 2, h = i & 3; float a = 0.f;
        for (int k = 0; k < 64; k++) a += ee1[t * 64 + k] * g_aew1T[h * 64 + k];
        g_eea1[i] = a;
    } else if (i < 32) {
        int j = i - 16; int t = j >> 2, h = j & 3; float a = 0.f;
        for (int k = 0; k < 64; k++) a += ee2[t * 64 + k] * g_aew2T[h * 64 + k];
        g_eea2[j] = a;
    }
}

// fp16 copies of all weights
__global__ void k_pre_w(const float* __restrict__ w2, const float* __restrict__ wres2,
                        const float* __restrict__ w1, const float* __restrict__ wres1) {
    int i = blockIdx.x * blockDim.x + threadIdx.x;
    if (i < 65536) g_w2h[i] = __float2half(w2[i]);
    else if (i < 81920) g_wresh[i - 65536] = __float2half(wres2[i - 65536]);
    else if (i < 86016) g_w1h[i - 81920] = __float2half(w1[i - 81920]);
    else if (i < 90112) g_wres1h[i - 86016] = __float2half(wres1[i - 86016]);
}

// ---------------- layer 1 GEMM: 64-row tile, fp16 HMMA, 3 CTA/SM ------------------
__global__ void __launch_bounds__(256, 3)
k_gemm1(const float* __restrict__ x, const int* __restrict__ nt,
        const float* __restrict__ b1,
        const float* __restrict__ asrc, const float* __restrict__ adst, int N) {
    extern __shared__ __align__(16) char smraw[];
    __half* XH = reinterpret_cast<__half*>(smraw);            // [64][40]
    __half* WH = reinterpret_cast<__half*>(smraw + 5120);     // [32][136]
    float*  Dsm = reinterpret_cast<float*>(smraw);            // [64][130] (after)
    float*  sA = reinterpret_cast<float*>(smraw + 33280);
    float*  sD = reinterpret_cast<float*>(smraw + 33792);
    int t = threadIdx.x;           // 256
    int r0 = blockIdx.x * 64;
    int ct = blockIdx.y;           // 0: w1 + sd dots, 1: wres1 + acc zeroing
    int lane = t & 31, w = t >> 5;
    int warpM = w >> 2, warpN = w & 3;

    if (ct == 0 && t < 128) { sA[t] = asrc[t]; sD[t] = adst[t]; }

    {
        int r = t >> 2, kc = (t & 3) * 8;
        int gr = r0 + r;
        __half2 hh[4];
        if (gr < N) {
            float4 xa = *reinterpret_cast<const float4*>(&x[(size_t)gr * 32 + kc]);
            float4 xb = *reinterpret_cast<const float4*>(&x[(size_t)gr * 32 + kc + 4]);
            hh[0] = __floats2half2_rn(xa.x, xa.y);
            hh[1] = __floats2half2_rn(xa.z, xa.w);
            hh[2] = __floats2half2_rn(xb.x, xb.y);
            hh[3] = __floats2half2_rn(xb.z, xb.w);
        } else {
            hh[0] = hh[1] = hh[2] = hh[3] = __floats2half2_rn(0.f, 0.f);
        }
        *reinterpret_cast<uint4*>(&XH[r * 40 + kc]) = *reinterpret_cast<uint4*>(hh);
    }
    {
        const __half* wsrc = ct ? g_wres1h : g_w1h;
        for (int i = t; i < 512; i += 256) {
            int k = i >> 4, c8 = (i & 15) * 8;
            *reinterpret_cast<uint4*>(&WH[k * 136 + c8]) =
                *reinterpret_cast<const uint4*>(&wsrc[k * 128 + c8]);
        }
    }
    __syncthreads();

    float d[2][4][4];
    #pragma unroll
    for (int mf = 0; mf < 2; mf++)
        #pragma unroll
        for (int nf = 0; nf < 4; nf++)
            #pragma unroll
            for (int p = 0; p < 4; p++) d[mf][nf][p] = 0.f;

    uint32_t xh_b = smem_u32(XH);
    uint32_t wh_b = smem_u32(WH);
    int arow = lane & 15, acol = (lane >> 4) << 3;
    #pragma unroll
    for (int ks = 0; ks < 2; ks++) {
        int k0 = ks * 16;
        uint32_t a[2][4], b[4][2];
        #pragma unroll
        for (int mf = 0; mf < 2; mf++) {
            int m = warpM * 32 + mf * 16 + arow;
            ldsm_x4(a[mf], xh_b + (uint32_t)(m * 40 + k0 + acol) * 2u);
        }
        #pragma unroll
        for (int nf = 0; nf < 4; nf++) {
            int kk = k0 + (lane & 15);
            int n = warpN * 32 + nf * 8;
            ldsm_x2t(b[nf], wh_b + (uint32_t)(kk * 136 + n) * 2u);
        }
        #pragma unroll
        for (int mf = 0; mf < 2; mf++)
            #pragma unroll
            for (int nf = 0; nf < 4; nf++)
                mma16816(d[mf][nf], a[mf], b[nf]);
    }

    __syncthreads();
    #pragma unroll
    for (int mf = 0; mf < 2; mf++)
        #pragma unroll
        for (int nf = 0; nf < 4; nf++) {
            int row = warpM * 32 + mf * 16 + (lane >> 2);
            int col = warpN * 32 + nf * 8 + (lane & 3) * 2;
            *reinterpret_cast<float2*>(&Dsm[row * 130 + col]) =
                make_float2(d[mf][nf][0], d[mf][nf][1]);
            *reinterpret_cast<float2*>(&Dsm[(row + 8) * 130 + col]) =
                make_float2(d[mf][nf][2], d[mf][nf][3]);
        }
    __syncthreads();

    int tc = t & 15, tr = t >> 4;
    if (ct == 0) {
        float av[8], dv[8];
        #pragma unroll
        for (int i = 0; i < 8; i++) { av[i] = sA[tc * 8 + i]; dv[i] = sD[tc * 8 + i]; }
        int head = tc >> 2;
        #pragma unroll
        for (int j = 0; j < 4; j++) {
            int gr = r0 + tr * 4 + j;
            float o[8];
            const float* dr = &Dsm[(tr * 4 + j) * 130 + tc * 8];
            #pragma unroll
            for (int i = 0; i < 8; i++) o[i] = dr[i];
            int ty = (gr < N) ? nt[gr] : 0;
            const float* bias = &g_ne1w1[ty * 128 + tc * 8];
            float sp = 0.f, dp = 0.f;
            #pragma unroll
            for (int i = 0; i < 8; i++) {
                o[i] += bias[i];
                sp += o[i] * av[i];
                dp += o[i] * dv[i];
            }
            sp += __shfl_xor_sync(0xffffffffu, sp, 1);
            sp += __shfl_xor_sync(0xffffffffu, sp, 2);
            dp += __shfl_xor_sync(0xffffffffu, dp, 1);
            dp += __shfl_xor_sync(0xffffffffu, dp, 2);
            if (gr < N) {
                __half2 hh[4];
                #pragma unroll
                for (int p = 0; p < 4; p++) hh[p] = __floats2half2_rn(o[2 * p], o[2 * p + 1]);
                *reinterpret_cast<uint4*>(&g_h1h[(size_t)gr * 128 + tc * 8]) =
                    *reinterpret_cast<uint4*>(hh);
                if ((tc & 3) == 0) {
                    g_s[gr * 4 + head] = sp; g_d[gr * 4 + head] = dp;
                    g_den[gr * 4 + head] = 0.f;
                }
            }
        }
    } else {
        float bb[8];
        #pragma unroll
        for (int i = 0; i < 8; i++) bb[i] = b1[tc * 8 + i];
        float4 z4 = make_float4(0.f, 0.f, 0.f, 0.f);
        #pragma unroll
        for (int j = 0; j < 4; j++) {
            int gr = r0 + tr * 4 + j; if (gr >= N) continue;
            float o[8];
            const float* dr = &Dsm[(tr * 4 + j) * 130 + tc * 8];
            #pragma unroll
            for (int i = 0; i < 8; i++) o[i] = dr[i];
            float* dst = &g_res[(size_t)gr * 128 + tc * 8];
            *reinterpret_cast<float4*>(dst) =
                make_float4(o[0] + bb[0], o[1] + bb[1], o[2] + bb[2], o[3] + bb[3]);
            *reinterpret_cast<float4*>(dst + 4) =
                make_float4(o[4] + bb[4], o[5] + bb[5], o[6] + bb[6], o[7] + bb[7]);
            float* az = &g_acc1[(size_t)gr * 128 + tc * 8];
            *reinterpret_cast<float4*>(az)     = z4;
            *reinterpret_cast<float4*>(az + 4) = z4;
        }
    }
}

// ---------------- layer 1 fused edge phase (unchanged best) -----------------------
__global__ void __launch_bounds__(256)
k_edge1(const int* __restrict__ src, const int* __restrict__ dst,
        const float* __restrict__ ea, const int* __restrict__ et, int E) {
    __shared__ __align__(16) float sa1[4][64], sa2[4][64];
    __shared__ float se1[16], se2[16];
    int t = threadIdx.x;
    sa1[t >> 6][t & 63] = g_aew1T[t];
    sa2[t >> 6][t & 63] = g_aew2T[t];
    if (t < 16) { se1[t] = g_eea1[t]; se2[t] = g_eea2[t]; }
    __syncthreads();
    int l = t & 31, li = l & 7;
    int e = blockIdx.x * 32 + (t >> 5) * 4 + (l >> 3);
    bool valid = e < E;
    float e1[4] = {0, 0, 0, 0}, e2[4] = {0, 0, 0, 0};
    int s_ = 0, d_ = 0;
    if (valid) {
        s_ = src[e]; d_ = dst[e];
        const float* row = ea + (size_t)e * 64 + li * 8;
        float4 va = *reinterpret_cast<const float4*>(row);
        float4 vb = *reinterpret_cast<const float4*>(row + 4);
        float vs[8] = {va.x, va.y, va.z, va.w, vb.x, vb.y, vb.z, vb.w};
        #pragma unroll
        for (int h = 0; h < 4; h++) {
            float4 w0 = *reinterpret_cast<const float4*>(&sa1[h][li * 8]);
            float4 w1v = *reinterpret_cast<const float4*>(&sa1[h][li * 8 + 4]);
            float4 u0 = *reinterpret_cast<const float4*>(&sa2[h][li * 8]);
            float4 u1 = *reinterpret_cast<const float4*>(&sa2[h][li * 8 + 4]);
            e1[h] = vs[0]*w0.x + vs[1]*w0.y + vs[2]*w0.z + vs[3]*w0.w
                  + vs[4]*w1v.x + vs[5]*w1v.y + vs[6]*w1v.z + vs[7]*w1v.w;
            e2[h] = vs[0]*u0.x + vs[1]*u0.y + vs[2]*u0.z + vs[3]*u0.w
                  + vs[4]*u1.x + vs[5]*u1.y + vs[6]*u1.z + vs[7]*u1.w;
        }
    }
    #pragma unroll
    for (int h = 0; h < 4; h++)
        #pragma unroll
        for (int o = 1; o < 8; o <<= 1) {
            e1[h] += __shfl_xor_sync(0xffffffffu, e1[h], o);
            e2[h] += __shfl_xor_sync(0xffffffffu, e2[h], o);
        }
    float ex = 0.f;
    if (valid && li < 4) {
        float ev1 = (li == 0) ? e1[0] : (li == 1) ? e1[1] : (li == 2) ? e1[2] : e1[3];
        float ev2 = (li == 0) ? e2[0] : (li == 1) ? e2[1] : (li == 2) ? e2[2] : e2[3];
        int ty = et[e];
        float a = g_s[s_ * 4 + li] + g_d[d_ * 4 + li] + ev1 + se1[ty * 4 + li];
        a = (a >= 0.f) ? a : 0.2f * a;
        ex = __expf(a);
        atomicAdd(&g_den[d_ * 4 + li], ex);
        g_e2[e * 4 + li] = ev2 + se2[ty * 4 + li];
    }
    float exh = __shfl_sync(0xffffffffu, ex, (l & 24) + (li >> 1));
    if (valid) {
        const uint4* hb = reinterpret_cast<const uint4*>(&g_h1h[(size_t)s_ * 128 + li * 16]);
        float* ab = &g_acc1[(size_t)d_ * 128 + li * 16];
        #pragma unroll
        for (int q = 0; q < 2; q++) {
            uint4 pk = hb[q];
            __half2* hp = reinterpret_cast<__half2*>(&pk);
            float2 f0 = __half22float2(hp[0]);
            float2 f1 = __half22float2(hp[1]);
            float2 f2 = __half22float2(hp[2]);
            float2 f3 = __half22float2(hp[3]);
            red4(ab + q * 8,     f0.x * exh, f0.y * exh, f1.x * exh, f1.y * exh);
            red4(ab + q * 8 + 4, f2.x * exh, f2.y * exh, f3.x * exh, f3.y * exh);
        }
    }
}

// ---------------- BN stats: y = acc1/den + res (softmax norm fused) --------------
__global__ void k_bnstats(int N) {
    int t = threadIdx.x;
    int hh = t >> 5;
    double s = 0.0, q = 0.0;
    for (int n = blockIdx.x; n < N; n += gridDim.x) {
        float den = g_den[n * 4 + hh] + 1e-16f;
        float y = g_acc1[(size_t)n * 128 + t] / den + g_res[(size_t)n * 128 + t];
        g_acc1[(size_t)n * 128 + t] = y;
        s += y; q += (double)y * y;
    }
    atomicAdd(&g_colsum[t], s);
    atomicAdd(&g_colsq[t], q);
}

// BN finalize once (1 block, DP)
__global__ void k_bnfin(const float* __restrict__ gamma, const float* __restrict__ beta, int N) {
    int t = threadIdx.x;
    double mu = g_colsum[t] / N;
    double var = g_colsq[t] / N - mu * mu;
    double sc = (double)gamma[t] / sqrt(var + 1e-5);
    g_scale[t] = (float)sc;
    g_shift[t] = (float)((double)beta[t] - mu * sc);
}

// apply BN once, write fp16 gemm2 input (float math only)
__global__ void k_bnapply(int N) {
    int i = blockIdx.x * blockDim.x + threadIdx.x;   // one uint4 (8 halves) per thread
    if (i >= N * 16) return;
    int kc = (i & 15) * 8;
    size_t base = (size_t)(i >> 4) * 128 + kc;
    float4 xa = *reinterpret_cast<const float4*>(&g_acc1[base]);
    float4 xb = *reinterpret_cast<const float4*>(&g_acc1[base + 4]);
    __half2 hh[4];
    hh[0] = __floats2half2_rn(xa.x * g_scale[kc]     + g_shift[kc],
                              xa.y * g_scale[kc + 1] + g_shift[kc + 1]);
    hh[1] = __floats2half2_rn(xa.z * g_scale[kc + 2] + g_shift[kc + 2],
                              xa.w * g_scale[kc + 3] + g_shift[kc + 3]);
    hh[2] = __floats2half2_rn(xb.x * g_scale[kc + 4] + g_shift[kc + 4],
                              xb.y * g_scale[kc + 5] + g_shift[kc + 5]);
    hh[3] = __floats2half2_rn(xb.z * g_scale[kc + 6] + g_shift[kc + 6],
                              xb.w * g_scale[kc + 7] + g_shift[kc + 7]);
    *reinterpret_cast<uint4*>(&g_xh2[base]) = *reinterpret_cast<uint4*>(hh);
}

// ---------------- layer 2 GEMM: fp16 tensor-core; ct=4 writes res2 -> d_out -------
__global__ void __launch_bounds__(256, 2)
k_gemm2(const int* __restrict__ nt, const float* __restrict__ b2,
        const float* __restrict__ asrc, const float* __restrict__ adst,
        float* __restrict__ outp, int N) {
    extern __shared__ __align__(16) char smraw[];
    __half* XH = reinterpret_cast<__half*>(smraw);                  // [128][136]
    __half* WH = reinterpret_cast<__half*>(smraw + 34816);          // [128][136]
    float*  Dsm = reinterpret_cast<float*>(smraw);                  // [128][130] (after)
    int t = threadIdx.x;
    int r0 = blockIdx.x * 128;
    int ct = blockIdx.y;
    int lane = t & 31, w = t >> 5;
    int warpM = w >> 2, warpN = w & 3;

    for (int i = t; i < 2048; i += 256) {
        int r = i >> 4, c8 = (i & 15) * 8;
        int gr = r0 + r;
        uint4 v = make_uint4(0u, 0u, 0u, 0u);
        if (gr < N) v = *reinterpret_cast<const uint4*>(&g_xh2[(size_t)gr * 128 + c8]);
        *reinterpret_cast<uint4*>(&XH[r * 136 + c8]) = v;
    }
    {
        const __half* wsrc = (ct < 4) ? &g_w2h[ct * 128] : g_wresh;
        int wstride = (ct < 4) ? 512 : 128;
        for (int i = t; i < 2048; i += 256) {
            int k = i >> 4, c8 = (i & 15) * 8;
            *reinterpret_cast<uint4*>(&WH[k * 136 + c8]) =
                *reinterpret_cast<const uint4*>(&wsrc[(size_t)k * wstride + c8]);
        }
    }
    __syncthreads();

    float d[4][4][4];
    #pragma unroll
    for (int mf = 0; mf < 4; mf++)
        #pragma unroll
        for (int nf = 0; nf < 4; nf++)
            #pragma unroll
            for (int p = 0; p < 4; p++) d[mf][nf][p] = 0.f;

    uint32_t xh_b = smem_u32(XH);
    uint32_t wh_b = smem_u32(WH);
    int arow = lane & 15, acol = (lane >> 4) << 3;
    #pragma unroll
    for (int ks = 0; ks < 8; ks++) {
        int k0 = ks * 16;
        uint32_t a[4][4], b[4][2];
        #pragma unroll
        for (int mf = 0; mf < 4; mf++) {
            int m = warpM * 64 + mf * 16 + arow;
            ldsm_x4(a[mf], xh_b + (uint32_t)(m * 136 + k0 + acol) * 2u);
        }
        #pragma unroll
        for (int nf = 0; nf < 4; nf++) {
            int kk = k0 + (lane & 15);
            int n = warpN * 32 + nf * 8;
            ldsm_x2t(b[nf], wh_b + (uint32_t)(kk * 136 + n) * 2u);
        }
        #pragma unroll
        for (int mf = 0; mf < 4; mf++)
            #pragma unroll
            for (int nf = 0; nf < 4; nf++)
                mma16816(d[mf][nf], a[mf], b[nf]);
    }

    __syncthreads();
    #pragma unroll
    for (int mf = 0; mf < 4; mf++)
        #pragma unroll
        for (int nf = 0; nf < 4; nf++) {
            int row = warpM * 64 + mf * 16 + (lane >> 2);
            int col = warpN * 32 + nf * 8 + (lane & 3) * 2;
            *reinterpret_cast<float2*>(&Dsm[row * 130 + col]) =
                make_float2(d[mf][nf][0], d[mf][nf][1]);
            *reinterpret_cast<float2*>(&Dsm[(row + 8) * 130 + col]) =
                make_float2(d[mf][nf][2], d[mf][nf][3]);
        }
    __syncthreads();

    int tc = t & 15, tr = t >> 4;
    if (ct < 4) {
        float av[8], dv[8];
        #pragma unroll
        for (int i = 0; i < 8; i++) {
            av[i] = asrc[ct * 128 + tc * 8 + i];
            dv[i] = adst[ct * 128 + tc * 8 + i];
        }
        #pragma unroll
        for (int j = 0; j < 8; j++) {
            int gr = r0 + tr * 8 + j;
            float o[8];
            const float* dr = &Dsm[(tr * 8 + j) * 130 + tc * 8];
            #pragma unroll
            for (int i = 0; i < 8; i++) o[i] = dr[i];
            int ty = (gr < N) ? nt[gr] : 0;
            const float* bias = &g_ne2w2[ty * 512 + ct * 128 + tc * 8];
            float sp = 0.f, dp = 0.f;
            #pragma unroll
            for (int i = 0; i < 8; i++) {
                o[i] += bias[i];
                sp += o[i] * av[i];
                dp += o[i] * dv[i];
            }
            #pragma unroll
            for (int off = 8; off; off >>= 1) {
                sp += __shfl_xor_sync(0xffffffffu, sp, off);
                dp += __shfl_xor_sync(0xffffffffu, dp, off);
            }
            if (gr < N) {
                __half2 hh[4];
                #pragma unroll
                for (int p = 0; p < 4; p++) hh[p] = __floats2half2_rn(o[2 * p], o[2 * p + 1]);
                *reinterpret_cast<uint4*>(&g_h2h[(size_t)gr * 512 + ct * 128 + tc * 8]) =
                    *reinterpret_cast<uint4*>(hh);
                if (tc == 0) {
                    g_s[gr * 4 + ct] = sp; g_d[gr * 4 + ct] = dp;
                    g_den[gr * 4 + ct] = 0.f;
                }
            }
        }
    } else {
        #pragma unroll
        for (int j = 0; j < 8; j++) {
            int gr = r0 + tr * 8 + j; if (gr >= N) continue;
            float o[8];
            const float* dr = &Dsm[(tr * 8 + j) * 130 + tc * 8];
            #pragma unroll
            for (int i = 0; i < 8; i++) o[i] = dr[i];
            const float* bias = &b2[tc * 8];
            float* dst = &outp[(size_t)gr * 128 + tc * 8];
            *reinterpret_cast<float4*>(dst) =
                make_float4(o[0] + bias[0], o[1] + bias[1], o[2] + bias[2], o[3] + bias[3]);
            *reinterpret_cast<float4*>(dst + 4) =
                make_float4(o[4] + bias[4], o[5] + bias[5], o[6] + bias[6], o[7] + bias[7]);
        }
    }
}

// ---------------- layer 2 edge pass A (round-13 proven form) -----------------------
__global__ void k_edge2A(const int* __restrict__ src, const int* __restrict__ dst, int E) {
    int i = blockIdx.x * blockDim.x + threadIdx.x;
    if (i >= E * 4) return;
    int e = i >> 2, h = i & 3;
    int s_ = src[e], d_ = dst[e];
    float a = g_s[s_ * 4 + h] + g_d[d_ * 4 + h] + g_e2[i];
    a = (a >= 0.f) ? a : 0.2f * a;
    float ex = __expf(a);
    g_alpha[i] = ex;
    atomicAdd(&g_den[d_ * 4 + h], ex);
}

// ---------------- edge aggregate layer 2: red4 directly into d_out ----------------
__global__ void k_aggr2(const int* __restrict__ src, const int* __restrict__ dst,
                        float* __restrict__ outp, int E) {
    int e = blockIdx.x * 8 + (threadIdx.x >> 5); if (e >= E) return;
    int l = threadIdx.x & 31;
    int s_ = src[e], d_ = dst[e];
    float cf = 0.f;
    if (l < 4) cf = 0.25f * g_alpha[e * 4 + l] / (g_den[d_ * 4 + l] + 1e-16f);
    int m = l & 15, hp = l >> 4;
    float ca = __shfl_sync(0xffffffffu, cf, 2 * hp);
    float cb = __shfl_sync(0xffffffffu, cf, 2 * hp + 1);
    const uint4* hs = reinterpret_cast<const uint4*>(&g_h2h[(size_t)s_ * 512]);
    uint4 qa = hs[hp * 32 + m];
    uint4 qb = hs[hp * 32 + 16 + m];
    __half2* pa = reinterpret_cast<__half2*>(&qa);
    __half2* pb = reinterpret_cast<__half2*>(&qb);
    float r[8];
    #pragma unroll
    for (int i = 0; i < 4; i++) {
        float2 fa = __half22float2(pa[i]);
        float2 fb = __half22float2(pb[i]);
        r[2 * i]     = ca * fa.x + cb * fb.x;
        r[2 * i + 1] = ca * fa.y + cb * fb.y;
    }
    #pragma unroll
    for (int i = 0; i < 8; i++) r[i] += __shfl_xor_sync(0xffffffffu, r[i], 16);
    if (l < 16) {
        float* ab = &outp[(size_t)d_ * 128 + m * 8];
        red4(ab,     r[0], r[1], r[2], r[3]);
        red4(ab + 4, r[4], r[5], r[6], r[7]);
    }
}

// ---------------- host launch ----------------------------------------------------
extern "C" void kernel_launch(void* const* d_in, const int* in_sizes, int n_in,
                              void* d_out, int out_size) {
    const float* x      = (const float*)d_in[0];
    const int*   ei     = (const int*)  d_in[1];
    const int*   nt     = (const int*)  d_in[2];
    const float* ea     = (const float*)d_in[3];
    const int*   et     = (const int*)  d_in[4];
    const float* ne1    = (const float*)d_in[5];
    const float* w1     = (const float*)d_in[6];
    const float* we1    = (const float*)d_in[7];
    const float* asrc1  = (const float*)d_in[8];
    const float* adst1  = (const float*)d_in[9];
    const float* aedge1 = (const float*)d_in[10];
    const float* ee1    = (const float*)d_in[11];
    const float* wres1  = (const float*)d_in[12];
    const float* b1     = (const float*)d_in[13];
    const float* gamma  = (const float*)d_in[14];
    const float* beta   = (const float*)d_in[15];
    const float* ne2    = (const float*)d_in[16];
    const float* w2     = (const float*)d_in[17];
    const float* we2    = (const float*)d_in[18];
    const float* asrc2  = (const float*)d_in[19];
    const float* adst2  = (const float*)d_in[20];
    const float* aedge2 = (const float*)d_in[21];
    const float* ee2    = (const float*)d_in[22];
    const float* wres2  = (const float*)d_in[23];
    const float* b2     = (const float*)d_in[24];

    int N = in_sizes[0] / 32;
    int E = in_sizes[4];
    const int* src = ei;
    const int* dstp = ei + E;
    float* outp = (float*)d_out;

    // ---- precompute ----
    k_pre_a<<<10, 256>>>(we1, aedge1, we2, aedge2, ne1, w1, ne2, w2);
    k_pre_b<<<1, 32>>>(ee1, ee2);
    k_pre_w<<<352, 256>>>(w2, wres2, w1, wres1);

    // ---- layer 1 (tensor-core gemm1, 64-row tiles) ----
    size_t smem1 = 34304;
    cudaFuncSetAttribute(k_gemm1, cudaFuncAttributeMaxDynamicSharedMemorySize, (int)smem1);
    dim3 g1((N + 63) / 64, 2);
    k_gemm1<<<g1, 256, smem1>>>(x, nt, b1, asrc1, adst1, N);
    k_edge1<<<(E + 31) / 32, 256>>>(src, dstp, ea, et, E);

    // ---- batch norm (stats, finalize once, apply) ----
    k_bnstats<<<592, 128>>>(N);
    k_bnfin<<<1, 128>>>(gamma, beta, N);
    k_bnapply<<<(N * 16 + 255) / 256, 256>>>(N);

    // ---- layer 2 (tensor-core gemm2; ct=4 writes res2 into d_out) ----
    size_t smem2 = 69632;
    cudaFuncSetAttribute(k_gemm2, cudaFuncAttributeMaxDynamicSharedMemorySize, (int)smem2);
    dim3 g2((N + 127) / 128, 5);
    k_gemm2<<<g2, 256, smem2>>>(nt, b2, asrc2, adst2, outp, N);
    k_edge2A<<<(E * 4 + 255) / 256, 256>>>(src, dstp, E);
    k_aggr2<<<(E + 7) / 8, 256>>>(src, dstp, outp, E);
}

// round 17
// speedup vs baseline: 1.1159x; 1.0694x over previous
#include <cuda_runtime.h>
#include <cuda_fp16.h>
#include <math.h>
#include <stdint.h>

// ---------------- problem-size bounds (N=50000, E=400000 in dataset) ----------
#define MAXN 50176
#define MAXE 400384

// ---------------- device scratch (no mallocs allowed) -------------------------
__device__ __half  g_h1h[MAXN * 128];            // layer1 node embeddings (fp16)
__device__ __half  g_resh[MAXN * 128];           // residual res1 (fp16)
__device__ float  g_acc1[MAXN * 128];            // layer1 aggregate
__device__ __half  g_xh2[MAXN * 128];            // y then BN(y) fp16 (gemm2 input)
__device__ __half  g_h2h[(size_t)MAXN * 512];    // layer2 node embeddings (fp16)
__device__ float  g_s[MAXN * 4], g_d[MAXN * 4];  // attention src/dst terms
__device__ float  g_den[MAXN * 4];
__device__ float  g_alpha[MAXE * 4];             // layer2 ex values
__device__ float  g_e2[MAXE * 4];                // layer2 edge attention term
__device__ double g_colsum[128], g_colsq[128];
__device__ float  g_scale[128], g_shift[128];
__device__ float  g_aew1T[4 * 64], g_aew2T[4 * 64];  // transposed [h][k]
__device__ float  g_eea1[4 * 4],  g_eea2[4 * 4];
__device__ float  g_ne1w1[3 * 128], g_ne2w2[3 * 512];
__device__ __half g_w2h[128 * 512];              // fp16 copies of weights
__device__ __half g_wresh[128 * 128];
__device__ __half g_w1h[32 * 128];
__device__ __half g_wres1h[32 * 128];

// ---------------- helpers ------------------------------------------------------
__device__ __forceinline__ void red4(float* p, float a, float b, float c, float d) {
    asm volatile("red.global.add.v4.f32 [%0], {%1,%2,%3,%4};"
                 :: "l"(p), "f"(a), "f"(b), "f"(c), "f"(d) : "memory");
}
__device__ __forceinline__ uint32_t smem_u32(const void* p) {
    return (uint32_t)__cvta_generic_to_shared(p);
}
__device__ __forceinline__ void ldsm_x4(uint32_t* r, uint32_t addr) {
    asm volatile("ldmatrix.sync.aligned.m8n8.x4.shared.b16 {%0,%1,%2,%3}, [%4];"
                 : "=r"(r[0]), "=r"(r[1]), "=r"(r[2]), "=r"(r[3]) : "r"(addr));
}
__device__ __forceinline__ void ldsm_x2t(uint32_t* r, uint32_t addr) {
    asm volatile("ldmatrix.sync.aligned.m8n8.x2.trans.shared.b16 {%0,%1}, [%2];"
                 : "=r"(r[0]), "=r"(r[1]) : "r"(addr));
}
__device__ __forceinline__ void mma16816(float* d, const uint32_t* a, const uint32_t* b) {
    asm volatile("mma.sync.aligned.m16n8k16.row.col.f32.f16.f16.f32 "
                 "{%0,%1,%2,%3}, {%4,%5,%6,%7}, {%8,%9}, {%0,%1,%2,%3};"
                 : "+f"(d[0]), "+f"(d[1]), "+f"(d[2]), "+f"(d[3])
                 : "r"(a[0]), "r"(a[1]), "r"(a[2]), "r"(a[3]), "r"(b[0]), "r"(b[1]));
}

// ---------------- precompute: fold linear maps (+ zero colsum) ------------------
__global__ void k_pre_a(const float* __restrict__ we1, const float* __restrict__ aedge1,
                        const float* __restrict__ we2, const float* __restrict__ aedge2,
                        const float* __restrict__ ne1, const float* __restrict__ w1,
                        const float* __restrict__ ne2, const float* __restrict__ w2) {
    int i = blockIdx.x * blockDim.x + threadIdx.x;
    if (i < 128) { g_colsum[i] = 0.0; g_colsq[i] = 0.0; }
    if (i < 256) {
        int k = i >> 2, h = i & 3; float a = 0.f;
        for (int c = 0; c < 32; c++) a += we1[k * 128 + h * 32 + c] * aedge1[h * 32 + c];
        g_aew1T[h * 64 + k] = a;
    } else if (i < 512) {
        int j = i - 256; int k = j >> 2, h = j & 3; float a = 0.f;
        for (int c = 0; c < 128; c++) a += we2[k * 512 + h * 128 + c] * aedge2[h * 128 + c];
        g_aew2T[h * 64 + k] = a;
    } else if (i < 896) {
        int j = i - 512; int t = j >> 7, col = j & 127; float a = 0.f;
        for (int k = 0; k < 32; k++) a += ne1[t * 32 + k] * w1[k * 128 + col];
        g_ne1w1[j] = a;
    } else if (i < 2432) {
        int j = i - 896; int t = j >> 9, col = j & 511; float a = 0.f;
        for (int k = 0; k < 128; k++) a += ne2[t * 128 + k] * w2[k * 512 + col];
        g_ne2w2[j] = a;
    }
}

__global__ void k_pre_b(const float* __restrict__ ee1, const float* __restrict__ ee2) {
    int i = threadIdx.x;
    if (i < 16) {
        int t = i >> 2, h = i & 3; float a = 0.f;
        for (int k = 0; k < 64; k++) a += ee1[t * 64 + k] * g_aew1T[h * 64 + k];
        g_eea1[i] = a;
    } else if (i < 32) {
        int j = i - 16; int t = j >> 2, h = j & 3; float a = 0.f;
        for (int k = 0; k < 64; k++) a += ee2[t * 64 + k] * g_aew2T[h * 64 + k];
        g_eea2[j] = a;
    }
}

// fp16 copies of all weights
__global__ void k_pre_w(const float* __restrict__ w2, const float* __restrict__ wres2,
                        const float* __restrict__ w1, const float* __restrict__ wres1) {
    int i = blockIdx.x * blockDim.x + threadIdx.x;
    if (i < 65536) g_w2h[i] = __float2half(w2[i]);
    else if (i < 81920) g_wresh[i - 65536] = __float2half(wres2[i - 65536]);
    else if (i < 86016) g_w1h[i - 81920] = __float2half(w1[i - 81920]);
    else if (i < 90112) g_wres1h[i - 86016] = __float2half(wres1[i - 86016]);
}

// ---------------- layer 1 GEMM: 64-row tile, fp16 HMMA, 3 CTA/SM ------------------
__global__ void __launch_bounds__(256, 3)
k_gemm1(const float* __restrict__ x, const int* __restrict__ nt,
        const float* __restrict__ b1,
        const float* __restrict__ asrc, const float* __restrict__ adst, int N) {
    extern __shared__ __align__(16) char smraw[];
    __half* XH = reinterpret_cast<__half*>(smraw);            // [64][40]
    __half* WH = reinterpret_cast<__half*>(smraw + 5120);     // [32][136]
    float*  Dsm = reinterpret_cast<float*>(smraw);            // [64][130] (after)
    float*  sA = reinterpret_cast<float*>(smraw + 33280);
    float*  sD = reinterpret_cast<float*>(smraw + 33792);
    int t = threadIdx.x;           // 256
    int r0 = blockIdx.x * 64;
    int ct = blockIdx.y;           // 0: w1 + sd dots, 1: wres1 + acc zeroing
    int lane = t & 31, w = t >> 5;
    int warpM = w >> 2, warpN = w & 3;

    if (ct == 0 && t < 128) { sA[t] = asrc[t]; sD[t] = adst[t]; }

    {
        int r = t >> 2, kc = (t & 3) * 8;
        int gr = r0 + r;
        __half2 hh[4];
        if (gr < N) {
            float4 xa = *reinterpret_cast<const float4*>(&x[(size_t)gr * 32 + kc]);
            float4 xb = *reinterpret_cast<const float4*>(&x[(size_t)gr * 32 + kc + 4]);
            hh[0] = __floats2half2_rn(xa.x, xa.y);
            hh[1] = __floats2half2_rn(xa.z, xa.w);
            hh[2] = __floats2half2_rn(xb.x, xb.y);
            hh[3] = __floats2half2_rn(xb.z, xb.w);
        } else {
            hh[0] = hh[1] = hh[2] = hh[3] = __floats2half2_rn(0.f, 0.f);
        }
        *reinterpret_cast<uint4*>(&XH[r * 40 + kc]) = *reinterpret_cast<uint4*>(hh);
    }
    {
        const __half* wsrc = ct ? g_wres1h : g_w1h;
        for (int i = t; i < 512; i += 256) {
            int k = i >> 4, c8 = (i & 15) * 8;
            *reinterpret_cast<uint4*>(&WH[k * 136 + c8]) =
                *reinterpret_cast<const uint4*>(&wsrc[k * 128 + c8]);
        }
    }
    __syncthreads();

    float d[2][4][4];
    #pragma unroll
    for (int mf = 0; mf < 2; mf++)
        #pragma unroll
        for (int nf = 0; nf < 4; nf++)
            #pragma unroll
            for (int p = 0; p < 4; p++) d[mf][nf][p] = 0.f;

    uint32_t xh_b = smem_u32(XH);
    uint32_t wh_b = smem_u32(WH);
    int arow = lane & 15, acol = (lane >> 4) << 3;
    #pragma unroll
    for (int ks = 0; ks < 2; ks++) {
        int k0 = ks * 16;
        uint32_t a[2][4], b[4][2];
        #pragma unroll
        for (int mf = 0; mf < 2; mf++) {
            int m = warpM * 32 + mf * 16 + arow;
            ldsm_x4(a[mf], xh_b + (uint32_t)(m * 40 + k0 + acol) * 2u);
        }
        #pragma unroll
        for (int nf = 0; nf < 4; nf++) {
            int kk = k0 + (lane & 15);
            int n = warpN * 32 + nf * 8;
            ldsm_x2t(b[nf], wh_b + (uint32_t)(kk * 136 + n) * 2u);
        }
        #pragma unroll
        for (int mf = 0; mf < 2; mf++)
            #pragma unroll
            for (int nf = 0; nf < 4; nf++)
                mma16816(d[mf][nf], a[mf], b[nf]);
    }

    __syncthreads();
    #pragma unroll
    for (int mf = 0; mf < 2; mf++)
        #pragma unroll
        for (int nf = 0; nf < 4; nf++) {
            int row = warpM * 32 + mf * 16 + (lane >> 2);
            int col = warpN * 32 + nf * 8 + (lane & 3) * 2;
            *reinterpret_cast<float2*>(&Dsm[row * 130 + col]) =
                make_float2(d[mf][nf][0], d[mf][nf][1]);
            *reinterpret_cast<float2*>(&Dsm[(row + 8) * 130 + col]) =
                make_float2(d[mf][nf][2], d[mf][nf][3]);
        }
    __syncthreads();

    int tc = t & 15, tr = t >> 4;
    if (ct == 0) {
        float av[8], dv[8];
        #pragma unroll
        for (int i = 0; i < 8; i++) { av[i] = sA[tc * 8 + i]; dv[i] = sD[tc * 8 + i]; }
        int head = tc >> 2;
        #pragma unroll
        for (int j = 0; j < 4; j++) {
            int gr = r0 + tr * 4 + j;
            float o[8];
            const float* dr = &Dsm[(tr * 4 + j) * 130 + tc * 8];
            #pragma unroll
            for (int i = 0; i < 8; i++) o[i] = dr[i];
            int ty = (gr < N) ? nt[gr] : 0;
            const float* bias = &g_ne1w1[ty * 128 + tc * 8];
            float sp = 0.f, dp = 0.f;
            #pragma unroll
            for (int i = 0; i < 8; i++) {
                o[i] += bias[i];
                sp += o[i] * av[i];
                dp += o[i] * dv[i];
            }
            sp += __shfl_xor_sync(0xffffffffu, sp, 1);
            sp += __shfl_xor_sync(0xffffffffu, sp, 2);
            dp += __shfl_xor_sync(0xffffffffu, dp, 1);
            dp += __shfl_xor_sync(0xffffffffu, dp, 2);
            if (gr < N) {
                __half2 hh[4];
                #pragma unroll
                for (int p = 0; p < 4; p++) hh[p] = __floats2half2_rn(o[2 * p], o[2 * p + 1]);
                *reinterpret_cast<uint4*>(&g_h1h[(size_t)gr * 128 + tc * 8]) =
                    *reinterpret_cast<uint4*>(hh);
                if ((tc & 3) == 0) {
                    g_s[gr * 4 + head] = sp; g_d[gr * 4 + head] = dp;
                    g_den[gr * 4 + head] = 0.f;
                }
            }
        }
    } else {
        float bb[8];
        #pragma unroll
        for (int i = 0; i < 8; i++) bb[i] = b1[tc * 8 + i];
        float4 z4 = make_float4(0.f, 0.f, 0.f, 0.f);
        #pragma unroll
        for (int j = 0; j < 4; j++) {
            int gr = r0 + tr * 4 + j; if (gr >= N) continue;
            float o[8];
            const float* dr = &Dsm[(tr * 4 + j) * 130 + tc * 8];
            #pragma unroll
            for (int i = 0; i < 8; i++) o[i] = dr[i];
            __half2 hh[4];
            #pragma unroll
            for (int p = 0; p < 4; p++)
                hh[p] = __floats2half2_rn(o[2 * p] + bb[2 * p], o[2 * p + 1] + bb[2 * p + 1]);
            *reinterpret_cast<uint4*>(&g_resh[(size_t)gr * 128 + tc * 8]) =
                *reinterpret_cast<uint4*>(hh);
            float* az = &g_acc1[(size_t)gr * 128 + tc * 8];
            *reinterpret_cast<float4*>(az)     = z4;
            *reinterpret_cast<float4*>(az + 4) = z4;
        }
    }
}

// ---------------- layer 1 fused edge phase (unchanged best) -----------------------
__global__ void __launch_bounds__(256)
k_edge1(const int* __restrict__ src, const int* __restrict__ dst,
        const float* __restrict__ ea, const int* __restrict__ et, int E) {
    __shared__ __align__(16) float sa1[4][64], sa2[4][64];
    __shared__ float se1[16], se2[16];
    int t = threadIdx.x;
    sa1[t >> 6][t & 63] = g_aew1T[t];
    sa2[t >> 6][t & 63] = g_aew2T[t];
    if (t < 16) { se1[t] = g_eea1[t]; se2[t] = g_eea2[t]; }
    __syncthreads();
    int l = t & 31, li = l & 7;
    int e = blockIdx.x * 32 + (t >> 5) * 4 + (l >> 3);
    bool valid = e < E;
    float e1[4] = {0, 0, 0, 0}, e2[4] = {0, 0, 0, 0};
    int s_ = 0, d_ = 0;
    if (valid) {
        s_ = src[e]; d_ = dst[e];
        const float* row = ea + (size_t)e * 64 + li * 8;
        float4 va = *reinterpret_cast<const float4*>(row);
        float4 vb = *reinterpret_cast<const float4*>(row + 4);
        float vs[8] = {va.x, va.y, va.z, va.w, vb.x, vb.y, vb.z, vb.w};
        #pragma unroll
        for (int h = 0; h < 4; h++) {
            float4 w0 = *reinterpret_cast<const float4*>(&sa1[h][li * 8]);
            float4 w1v = *reinterpret_cast<const float4*>(&sa1[h][li * 8 + 4]);
            float4 u0 = *reinterpret_cast<const float4*>(&sa2[h][li * 8]);
            float4 u1 = *reinterpret_cast<const float4*>(&sa2[h][li * 8 + 4]);
            e1[h] = vs[0]*w0.x + vs[1]*w0.y + vs[2]*w0.z + vs[3]*w0.w
                  + vs[4]*w1v.x + vs[5]*w1v.y + vs[6]*w1v.z + vs[7]*w1v.w;
            e2[h] = vs[0]*u0.x + vs[1]*u0.y + vs[2]*u0.z + vs[3]*u0.w
                  + vs[4]*u1.x + vs[5]*u1.y + vs[6]*u1.z + vs[7]*u1.w;
        }
    }
    #pragma unroll
    for (int h = 0; h < 4; h++)
        #pragma unroll
        for (int o = 1; o < 8; o <<= 1) {
            e1[h] += __shfl_xor_sync(0xffffffffu, e1[h], o);
            e2[h] += __shfl_xor_sync(0xffffffffu, e2[h], o);
        }
    float ex = 0.f;
    if (valid && li < 4) {
        float ev1 = (li == 0) ? e1[0] : (li == 1) ? e1[1] : (li == 2) ? e1[2] : e1[3];
        float ev2 = (li == 0) ? e2[0] : (li == 1) ? e2[1] : (li == 2) ? e2[2] : e2[3];
        int ty = et[e];
        float a = g_s[s_ * 4 + li] + g_d[d_ * 4 + li] + ev1 + se1[ty * 4 + li];
        a = (a >= 0.f) ? a : 0.2f * a;
        ex = __expf(a);
        atomicAdd(&g_den[d_ * 4 + li], ex);
        g_e2[e * 4 + li] = ev2 + se2[ty * 4 + li];
    }
    float exh = __shfl_sync(0xffffffffu, ex, (l & 24) + (li >> 1));
    if (valid) {
        const uint4* hb = reinterpret_cast<const uint4*>(&g_h1h[(size_t)s_ * 128 + li * 16]);
        float* ab = &g_acc1[(size_t)d_ * 128 + li * 16];
        #pragma unroll
        for (int q = 0; q < 2; q++) {
            uint4 pk = hb[q];
            __half2* hp = reinterpret_cast<__half2*>(&pk);
            float2 f0 = __half22float2(hp[0]);
            float2 f1 = __half22float2(hp[1]);
            float2 f2 = __half22float2(hp[2]);
            float2 f3 = __half22float2(hp[3]);
            red4(ab + q * 8,     f0.x * exh, f0.y * exh, f1.x * exh, f1.y * exh);
            red4(ab + q * 8 + 4, f2.x * exh, f2.y * exh, f3.x * exh, f3.y * exh);
        }
    }
}

// ---------------- BN stats: y = acc1/den + res; write y fp16 to g_xh2 -------------
__global__ void k_bnstats(int N) {
    int t = threadIdx.x;
    int hh = t >> 5;
    double s = 0.0, q = 0.0;
    for (int n = blockIdx.x; n < N; n += gridDim.x) {
        float den = g_den[n * 4 + hh] + 1e-16f;
        float res = __half2float(g_resh[(size_t)n * 128 + t]);
        float y = g_acc1[(size_t)n * 128 + t] / den + res;
        g_xh2[(size_t)n * 128 + t] = __float2half_rn(y);
        s += y; q += (double)y * y;
    }
    atomicAdd(&g_colsum[t], s);
    atomicAdd(&g_colsq[t], q);
}

// BN finalize once (1 block, DP)
__global__ void k_bnfin(const float* __restrict__ gamma, const float* __restrict__ beta, int N) {
    int t = threadIdx.x;
    double mu = g_colsum[t] / N;
    double var = g_colsq[t] / N - mu * mu;
    double sc = (double)gamma[t] / sqrt(var + 1e-5);
    g_scale[t] = (float)sc;
    g_shift[t] = (float)((double)beta[t] - mu * sc);
}

// apply BN in place on fp16 y (float math only)
__global__ void k_bnapply(int N) {
    int i = blockIdx.x * blockDim.x + threadIdx.x;   // one uint4 (8 halves) per thread
    if (i >= N * 16) return;
    int kc = (i & 15) * 8;
    size_t base = (size_t)(i >> 4) * 128 + kc;
    uint4 pk = *reinterpret_cast<const uint4*>(&g_xh2[base]);
    __half2* hp = reinterpret_cast<__half2*>(&pk);
    __half2 hh[4];
    #pragma unroll
    for (int p = 0; p < 4; p++) {
        float2 f = __half22float2(hp[p]);
        hh[p] = __floats2half2_rn(f.x * g_scale[kc + 2 * p]     + g_shift[kc + 2 * p],
                                  f.y * g_scale[kc + 2 * p + 1] + g_shift[kc + 2 * p + 1]);
    }
    *reinterpret_cast<uint4*>(&g_xh2[base]) = *reinterpret_cast<uint4*>(hh);
}

// ---------------- layer 2 GEMM: fp16 tensor-core; ct=4 writes res2 -> d_out -------
__global__ void __launch_bounds__(256, 2)
k_gemm2(const int* __restrict__ nt, const float* __restrict__ b2,
        const float* __restrict__ asrc, const float* __restrict__ adst,
        float* __restrict__ outp, int N) {
    extern __shared__ __align__(16) char smraw[];
    __half* XH = reinterpret_cast<__half*>(smraw);                  // [128][136]
    __half* WH = reinterpret_cast<__half*>(smraw + 34816);          // [128][136]
    float*  Dsm = reinterpret_cast<float*>(smraw);                  // [128][130] (after)
    int t = threadIdx.x;
    int r0 = blockIdx.x * 128;
    int ct = blockIdx.y;
    int lane = t & 31, w = t >> 5;
    int warpM = w >> 2, warpN = w & 3;

    for (int i = t; i < 2048; i += 256) {
        int r = i >> 4, c8 = (i & 15) * 8;
        int gr = r0 + r;
        uint4 v = make_uint4(0u, 0u, 0u, 0u);
        if (gr < N) v = *reinterpret_cast<const uint4*>(&g_xh2[(size_t)gr * 128 + c8]);
        *reinterpret_cast<uint4*>(&XH[r * 136 + c8]) = v;
    }
    {
        const __half* wsrc = (ct < 4) ? &g_w2h[ct * 128] : g_wresh;
        int wstride = (ct < 4) ? 512 : 128;
        for (int i = t; i < 2048; i += 256) {
            int k = i >> 4, c8 = (i & 15) * 8;
            *reinterpret_cast<uint4*>(&WH[k * 136 + c8]) =
                *reinterpret_cast<const uint4*>(&wsrc[(size_t)k * wstride + c8]);
        }
    }
    __syncthreads();

    float d[4][4][4];
    #pragma unroll
    for (int mf = 0; mf < 4; mf++)
        #pragma unroll
        for (int nf = 0; nf < 4; nf++)
            #pragma unroll
            for (int p = 0; p < 4; p++) d[mf][nf][p] = 0.f;

    uint32_t xh_b = smem_u32(XH);
    uint32_t wh_b = smem_u32(WH);
    int arow = lane & 15, acol = (lane >> 4) << 3;
    #pragma unroll
    for (int ks = 0; ks < 8; ks++) {
        int k0 = ks * 16;
        uint32_t a[4][4], b[4][2];
        #pragma unroll
        for (int mf = 0; mf < 4; mf++) {
            int m = warpM * 64 + mf * 16 + arow;
            ldsm_x4(a[mf], xh_b + (uint32_t)(m * 136 + k0 + acol) * 2u);
        }
        #pragma unroll
        for (int nf = 0; nf < 4; nf++) {
            int kk = k0 + (lane & 15);
            int n = warpN * 32 + nf * 8;
            ldsm_x2t(b[nf], wh_b + (uint32_t)(kk * 136 + n) * 2u);
        }
        #pragma unroll
        for (int mf = 0; mf < 4; mf++)
            #pragma unroll
            for (int nf = 0; nf < 4; nf++)
                mma16816(d[mf][nf], a[mf], b[nf]);
    }

    __syncthreads();
    #pragma unroll
    for (int mf = 0; mf < 4; mf++)
        #pragma unroll
        for (int nf = 0; nf < 4; nf++) {
            int row = warpM * 64 + mf * 16 + (lane >> 2);
            int col = warpN * 32 + nf * 8 + (lane & 3) * 2;
            *reinterpret_cast<float2*>(&Dsm[row * 130 + col]) =
                make_float2(d[mf][nf][0], d[mf][nf][1]);
            *reinterpret_cast<float2*>(&Dsm[(row + 8) * 130 + col]) =
                make_float2(d[mf][nf][2], d[mf][nf][3]);
        }
    __syncthreads();

    int tc = t & 15, tr = t >> 4;
    if (ct < 4) {
        float av[8], dv[8];
        #pragma unroll
        for (int i = 0; i < 8; i++) {
            av[i] = asrc[ct * 128 + tc * 8 + i];
            dv[i] = adst[ct * 128 + tc * 8 + i];
        }
        #pragma unroll
        for (int j = 0; j < 8; j++) {
            int gr = r0 + tr * 8 + j;
            float o[8];
            const float* dr = &Dsm[(tr * 8 + j) * 130 + tc * 8];
            #pragma unroll
            for (int i = 0; i < 8; i++) o[i] = dr[i];
            int ty = (gr < N) ? nt[gr] : 0;
            const float* bias = &g_ne2w2[ty * 512 + ct * 128 + tc * 8];
            float sp = 0.f, dp = 0.f;
            #pragma unroll
            for (int i = 0; i < 8; i++) {
                o[i] += bias[i];
                sp += o[i] * av[i];
                dp += o[i] * dv[i];
            }
            #pragma unroll
            for (int off = 8; off; off >>= 1) {
                sp += __shfl_xor_sync(0xffffffffu, sp, off);
                dp += __shfl_xor_sync(0xffffffffu, dp, off);
            }
            if (gr < N) {
                __half2 hh[4];
                #pragma unroll
                for (int p = 0; p < 4; p++) hh[p] = __floats2half2_rn(o[2 * p], o[2 * p + 1]);
                *reinterpret_cast<uint4*>(&g_h2h[(size_t)gr * 512 + ct * 128 + tc * 8]) =
                    *reinterpret_cast<uint4*>(hh);
                if (tc == 0) {
                    g_s[gr * 4 + ct] = sp; g_d[gr * 4 + ct] = dp;
                    g_den[gr * 4 + ct] = 0.f;
                }
            }
        }
    } else {
        #pragma unroll
        for (int j = 0; j < 8; j++) {
            int gr = r0 + tr * 8 + j; if (gr >= N) continue;
            float o[8];
            const float* dr = &Dsm[(tr * 8 + j) * 130 + tc * 8];
            #pragma unroll
            for (int i = 0; i < 8; i++) o[i] = dr[i];
            const float* bias = &b2[tc * 8];
            float* dst = &outp[(size_t)gr * 128 + tc * 8];
            *reinterpret_cast<float4*>(dst) =
                make_float4(o[0] + bias[0], o[1] + bias[1], o[2] + bias[2], o[3] + bias[3]);
            *reinterpret_cast<float4*>(dst + 4) =
                make_float4(o[4] + bias[4], o[5] + bias[5], o[6] + bias[6], o[7] + bias[7]);
        }
    }
}

// ---------------- layer 2 edge pass A (round-13 proven form) -----------------------
__global__ void k_edge2A(const int* __restrict__ src, const int* __restrict__ dst, int E) {
    int i = blockIdx.x * blockDim.x + threadIdx.x;
    if (i >= E * 4) return;
    int e = i >> 2, h = i & 3;
    int s_ = src[e], d_ = dst[e];
    float a = g_s[s_ * 4 + h] + g_d[d_ * 4 + h] + g_e2[i];
    a = (a >= 0.f) ? a : 0.2f * a;
    float ex = __expf(a);
    g_alpha[i] = ex;
    atomicAdd(&g_den[d_ * 4 + h], ex);
}

// ---------------- edge aggregate layer 2: red4 directly into d_out ----------------
__global__ void k_aggr2(const int* __restrict__ src, const int* __restrict__ dst,
                        float* __restrict__ outp, int E) {
    int e = blockIdx.x * 8 + (threadIdx.x >> 5); if (e >= E) return;
    int l = threadIdx.x & 31;
    int s_ = src[e], d_ = dst[e];
    float cf = 0.f;
    if (l < 4) cf = 0.25f * g_alpha[e * 4 + l] / (g_den[d_ * 4 + l] + 1e-16f);
    int m = l & 15, hp = l >> 4;
    float ca = __shfl_sync(0xffffffffu, cf, 2 * hp);
    float cb = __shfl_sync(0xffffffffu, cf, 2 * hp + 1);
    const uint4* hs = reinterpret_cast<const uint4*>(&g_h2h[(size_t)s_ * 512]);
    uint4 qa = hs[hp * 32 + m];
    uint4 qb = hs[hp * 32 + 16 + m];
    __half2* pa = reinterpret_cast<__half2*>(&qa);
    __half2* pb = reinterpret_cast<__half2*>(&qb);
    float r[8];
    #pragma unroll
    for (int i = 0; i < 4; i++) {
        float2 fa = __half22float2(pa[i]);
        float2 fb = __half22float2(pb[i]);
        r[2 * i]     = ca * fa.x + cb * fb.x;
        r[2 * i + 1] = ca * fa.y + cb * fb.y;
    }
    #pragma unroll
    for (int i = 0; i < 8; i++) r[i] += __shfl_xor_sync(0xffffffffu, r[i], 16);
    if (l < 16) {
        float* ab = &outp[(size_t)d_ * 128 + m * 8];
        red4(ab,     r[0], r[1], r[2], r[3]);
        red4(ab + 4, r[4], r[5], r[6], r[7]);
    }
}

// ---------------- host launch ----------------------------------------------------
extern "C" void kernel_launch(void* const* d_in, const int* in_sizes, int n_in,
                              void* d_out, int out_size) {
    const float* x      = (const float*)d_in[0];
    const int*   ei     = (const int*)  d_in[1];
    const int*   nt     = (const int*)  d_in[2];
    const float* ea     = (const float*)d_in[3];
    const int*   et     = (const int*)  d_in[4];
    const float* ne1    = (const float*)d_in[5];
    const float* w1     = (const float*)d_in[6];
    const float* we1    = (const float*)d_in[7];
    const float* asrc1  = (const float*)d_in[8];
    const float* adst1  = (const float*)d_in[9];
    const float* aedge1 = (const float*)d_in[10];
    const float* ee1    = (const float*)d_in[11];
    const float* wres1  = (const float*)d_in[12];
    const float* b1     = (const float*)d_in[13];
    const float* gamma  = (const float*)d_in[14];
    const float* beta   = (const float*)d_in[15];
    const float* ne2    = (const float*)d_in[16];
    const float* w2     = (const float*)d_in[17];
    const float* we2    = (const float*)d_in[18];
    const float* asrc2  = (const float*)d_in[19];
    const float* adst2  = (const float*)d_in[20];
    const float* aedge2 = (const float*)d_in[21];
    const float* ee2    = (const float*)d_in[22];
    const float* wres2  = (const float*)d_in[23];
    const float* b2     = (const float*)d_in[24];

    int N = in_sizes[0] / 32;
    int E = in_sizes[4];
    const int* src = ei;
    const int* dstp = ei + E;
    float* outp = (float*)d_out;

    // ---- precompute ----
    k_pre_a<<<10, 256>>>(we1, aedge1, we2, aedge2, ne1, w1, ne2, w2);
    k_pre_b<<<1, 32>>>(ee1, ee2);
    k_pre_w<<<352, 256>>>(w2, wres2, w1, wres1);

    // ---- layer 1 (tensor-core gemm1, 64-row tiles) ----
    size_t smem1 = 34304;
    cudaFuncSetAttribute(k_gemm1, cudaFuncAttributeMaxDynamicSharedMemorySize, (int)smem1);
    dim3 g1((N + 63) / 64, 2);
    k_gemm1<<<g1, 256, smem1>>>(x, nt, b1, asrc1, adst1, N);
    k_edge1<<<(E + 31) / 32, 256>>>(src, dstp, ea, et, E);

    // ---- batch norm (stats + fp16 y, finalize once, in-place apply) ----
    k_bnstats<<<592, 128>>>(N);
    k_bnfin<<<1, 128>>>(gamma, beta, N);
    k_bnapply<<<(N * 16 + 255) / 256, 256>>>(N);

    // ---- layer 2 (tensor-core gemm2; ct=4 writes res2 into d_out) ----
    size_t smem2 = 69632;
    cudaFuncSetAttribute(k_gemm2, cudaFuncAttributeMaxDynamicSharedMemorySize, (int)smem2);
    dim3 g2((N + 127) / 128, 5);
    k_gemm2<<<g2, 256, smem2>>>(nt, b2, asrc2, adst2, outp, N);
    k_edge2A<<<(E * 4 + 255) / 256, 256>>>(src, dstp, E);
    k_aggr2<<<(E + 7) / 8, 256>>>(src, dstp, outp, E);
}